// round 9
// baseline (speedup 1.0000x reference)
#include <cuda_runtime.h>
#include <cstdint>
#include <math.h>

#define NE      8
#define HIDDEN  2048
#define INTER   4096
#define TOKENS  8192
#define SLOTS   (TOKENS * 2)
#define PADM    128
#define SLOTS_PAD (SLOTS + NE * PADM)   // 17408
#define MT      (SLOTS_PAD / PADM)      // 136
#define KC      32                      // K elems per pipeline chunk

// ---------------- scratch (device globals: allocation-free, ~285 MB total) ----------------
__device__ int   g_topk_idx[SLOTS];
__device__ float g_topk_w[SLOTS];
__device__ int   g_counts[NE];
__device__ int   g_off[NE + 1];
__device__ int   g_tok[SLOTS_PAD];
__device__ float g_coef[SLOTS_PAD];
__device__ float g_h[(size_t)SLOTS_PAD * INTER];   // ~285 MB

// ---------------- helpers ----------------
__device__ __forceinline__ uint32_t swz(uint32_t off) { return off ^ ((off >> 3) & 0x70); }

__device__ __forceinline__ float rna_tf32(float f) {
    uint32_t r;
    asm("cvt.rna.tf32.f32 %0, %1;" : "=r"(r) : "f"(f));
    return __uint_as_float(r);
}
__device__ __forceinline__ uint4 tf32x4(float4 v) {
    uint4 r;
    asm("cvt.rna.tf32.f32 %0, %1;" : "=r"(r.x) : "f"(v.x));
    asm("cvt.rna.tf32.f32 %0, %1;" : "=r"(r.y) : "f"(v.y));
    asm("cvt.rna.tf32.f32 %0, %1;" : "=r"(r.z) : "f"(v.z));
    asm("cvt.rna.tf32.f32 %0, %1;" : "=r"(r.w) : "f"(v.w));
    return r;
}
__device__ __forceinline__ uint4 as_u4(float4 v) { return *(uint4*)&v; }

// m16n8k8 tf32 mma: D/C fp32, A row-major, B col-major
__device__ __forceinline__ void mma8(float* c, const uint32_t* a, uint32_t b0, uint32_t b1) {
    asm volatile(
        "mma.sync.aligned.m16n8k8.row.col.f32.tf32.tf32.f32 "
        "{%0,%1,%2,%3},{%4,%5,%6,%7},{%8,%9},{%0,%1,%2,%3};"
        : "+f"(c[0]), "+f"(c[1]), "+f"(c[2]), "+f"(c[3])
        : "r"(a[0]), "r"(a[1]), "r"(a[2]), "r"(a[3]), "r"(b0), "r"(b1));
}

// ---------------- router (with fused expert counting) ----------------
__global__ __launch_bounds__(256) void router_kernel(const float* __restrict__ x,
                                                     const float* __restrict__ gw) {
    __shared__ float xs[HIDDEN];
    __shared__ float logits[NE];
    int t = blockIdx.x, tid = threadIdx.x;
    const float* xr = x + (size_t)t * HIDDEN;
    for (int i = tid; i < HIDDEN; i += 256) xs[i] = xr[i];
    __syncthreads();
    int w = tid >> 5, lane = tid & 31;
    const float* gr = gw + (size_t)w * HIDDEN;
    float s = 0.f;
    for (int i = lane; i < HIDDEN; i += 32) s += xs[i] * gr[i];
    #pragma unroll
    for (int o = 16; o; o >>= 1) s += __shfl_xor_sync(0xffffffffu, s, o);
    if (lane == 0) logits[w] = s;
    __syncthreads();
    if (tid == 0) {
        float m = logits[0];
        #pragma unroll
        for (int e = 1; e < NE; e++) m = fmaxf(m, logits[e]);
        float p[NE]; float sum = 0.f;
        #pragma unroll
        for (int e = 0; e < NE; e++) { p[e] = __expf(logits[e] - m); sum += p[e]; }
        float inv = 1.f / sum;
        #pragma unroll
        for (int e = 0; e < NE; e++) p[e] *= inv;
        int i1 = 0;
        #pragma unroll
        for (int e = 1; e < NE; e++) if (p[e] > p[i1]) i1 = e;
        int i2 = (i1 == 0) ? 1 : 0;
        #pragma unroll
        for (int e = 0; e < NE; e++) if (e != i1 && e != i2 && p[e] > p[i2]) i2 = e;
        g_topk_idx[2 * t] = i1;     g_topk_w[2 * t] = p[i1];
        g_topk_idx[2 * t + 1] = i2; g_topk_w[2 * t + 1] = p[i2];
        atomicAdd(&g_counts[i1], 1);
        atomicAdd(&g_counts[i2], 1);
    }
}

__global__ void zero_counts_kernel() { if (threadIdx.x < NE) g_counts[threadIdx.x] = 0; }

// build lists; each block also derives the expert offsets locally (no offsets kernel)
__global__ __launch_bounds__(256) void build_lists_kernel() {
    int e = blockIdx.x, tid = threadIdx.x, lane = tid & 31, wid = tid >> 5;
    __shared__ int wsum[8]; __shared__ int sbase; __shared__ int seg_end;
    if (tid == 0) {
        int o = 0, my = 0, tot = 0;
        #pragma unroll
        for (int i = 0; i < NE; i++) {
            int pad = ((g_counts[i] + PADM - 1) / PADM) * PADM;
            if (i == e) my = o;
            o += pad;
            if (i == e) tot = o;
        }
        sbase = my;
        seg_end = tot;
        g_off[e] = my;
        if (e == NE - 1) g_off[NE] = o;
    }
    __syncthreads();
    int seg0 = sbase, segend = seg_end;
    for (int base = 0; base < TOKENS; base += 256) {
        int t = base + tid; int match = 0; float c = 0.f;
        int i0 = g_topk_idx[2 * t], i1 = g_topk_idx[2 * t + 1];
        if (i0 == e) { match = 1; c = g_topk_w[2 * t]; }
        else if (i1 == e) { match = 1; c = g_topk_w[2 * t + 1]; }
        unsigned m = __ballot_sync(0xffffffffu, match);
        if (lane == 0) wsum[wid] = __popc(m);
        __syncthreads();
        int woff = 0, tot = 0;
        #pragma unroll
        for (int i = 0; i < 8; i++) { int v = wsum[i]; if (i < wid) woff += v; tot += v; }
        if (match) { int p = sbase + woff + __popc(m & ((1u << lane) - 1)); g_tok[p] = t; g_coef[p] = c; }
        __syncthreads();
        if (tid == 0) sbase += tot;
        __syncthreads();
    }
    // zero-fill tile padding
    for (int p = seg0 + g_counts[e] + tid; p < segend; p += 256) { g_tok[p] = 0; g_coef[p] = 0.f; }
}

// ---------------- GEMM1: g_h = silu(x@w1^T) * (x@w3^T) ----------------
// CTA tile: M=128, N=128 (each of w1,w3), K-chunk=32. 2-stage LDG->cvt->STS pipeline.
// stage layout: A[128x32] @0 (16KB), B1[128x32] @16384 (16KB), B3[128x32] @32768 (16KB)
#define G1_STAGE  49152
#define G1_SMEMSZ (2 * G1_STAGE + 512)

__global__ __launch_bounds__(256, 1) void gemm1_kernel(const float* __restrict__ x,
                                                       const float* __restrict__ w1,
                                                       const float* __restrict__ w3) {
    extern __shared__ char sm[];
    const int r0 = blockIdx.y * PADM;
    if (r0 >= g_off[NE]) return;
    int e = 0;
    #pragma unroll
    for (int i = 1; i < NE; i++) if (r0 >= g_off[i]) e = i;
    const int n0 = blockIdx.x * 128;
    const int tid = threadIdx.x, wid = tid >> 5, lane = tid & 31;
    int* rtok = (int*)(sm + 2 * G1_STAGE);
    if (tid < 128) rtok[tid] = g_tok[r0 + tid];
    __syncthreads();

    // loader: thread -> (row = lr + 32j, 16B chunk lc); swizzled offset advances +4096 per 32 rows
    const int lr = tid >> 3, lc = tid & 7;
    const uint32_t as0 = swz(lr * 128 + lc * 16);
    const float* ag[4];
    #pragma unroll
    for (int j = 0; j < 4; j++) ag[j] = x + (size_t)rtok[lr + 32 * j] * HIDDEN + lc * 4;
    const float* b1b = w1 + ((size_t)e * INTER + n0 + lr) * HIDDEN + lc * 4;
    const float* b3b = w3 + ((size_t)e * INTER + n0 + lr) * HIDDEN + lc * 4;

    float4 pA[4], pB1[4], pB3[4];
    auto prefetch = [&](int kc) {
        int k0 = kc * KC;
        #pragma unroll
        for (int j = 0; j < 4; j++) pA[j]  = __ldg((const float4*)(ag[j] + k0));
        #pragma unroll
        for (int j = 0; j < 4; j++) pB1[j] = __ldg((const float4*)(b1b + (size_t)(32 * j) * HIDDEN + k0));
        #pragma unroll
        for (int j = 0; j < 4; j++) pB3[j] = __ldg((const float4*)(b3b + (size_t)(32 * j) * HIDDEN + k0));
    };
    auto stage_store = [&](int st) {
        char* base = sm + st * G1_STAGE;
        #pragma unroll
        for (int j = 0; j < 4; j++) *(uint4*)(base + as0 + 4096 * j)         = tf32x4(pA[j]);
        #pragma unroll
        for (int j = 0; j < 4; j++) *(uint4*)(base + 16384 + as0 + 4096 * j) = tf32x4(pB1[j]);
        #pragma unroll
        for (int j = 0; j < 4; j++) *(uint4*)(base + 32768 + as0 + 4096 * j) = tf32x4(pB3[j]);
    };

    const int mw = wid & 1, nw = wid >> 1;       // 2M x 4N warps; warp = 64M x 32N (per matrix)
    const int r = lane >> 2, q = lane & 3;
    float accg[4][4][4] = {}, accu[4][4][4] = {};

    prefetch(0);
    const int NCk = HIDDEN / KC;   // 64
    for (int kc = 0; kc < NCk; kc++) {
        int st = kc & 1;
        __syncthreads();
        stage_store(st);
        __syncthreads();
        if (kc + 1 < NCk) prefetch(kc + 1);
        const char* A  = sm + st * G1_STAGE;
        const char* B1 = A + 16384;
        const char* B3 = A + 32768;
        #pragma unroll
        for (int k8 = 0; k8 < 4; k8++) {
            uint32_t a[4][4];
            const int col = (k8 * 8 + q) * 4;
            #pragma unroll
            for (int i = 0; i < 4; i++) {
                int row = mw * 64 + i * 16 + r;
                a[i][0] = *(const uint32_t*)(A + swz(row * 128 + col));
                a[i][1] = *(const uint32_t*)(A + swz((row + 8) * 128 + col));
                a[i][2] = *(const uint32_t*)(A + swz(row * 128 + col + 16));
                a[i][3] = *(const uint32_t*)(A + swz((row + 8) * 128 + col + 16));
            }
            #pragma unroll
            for (int j = 0; j < 4; j++) {
                int nr = nw * 32 + j * 8 + r;
                uint32_t b1a = *(const uint32_t*)(B1 + swz(nr * 128 + col));
                uint32_t b1b_ = *(const uint32_t*)(B1 + swz(nr * 128 + col + 16));
                uint32_t b3a = *(const uint32_t*)(B3 + swz(nr * 128 + col));
                uint32_t b3b_ = *(const uint32_t*)(B3 + swz(nr * 128 + col + 16));
                #pragma unroll
                for (int i = 0; i < 4; i++) {
                    mma8(accg[i][j], a[i], b1a, b1b_);
                    mma8(accu[i][j], a[i], b3a, b3b_);
                }
            }
        }
    }

    // epilogue: h = rna(silu(g) * u), stored tf32-rounded for gemm2
    #pragma unroll
    for (int i = 0; i < 4; i++) {
        int row0 = r0 + mw * 64 + i * 16 + r;
        #pragma unroll
        for (int j = 0; j < 4; j++) {
            int cg = n0 + nw * 32 + j * 8 + q * 2;
            float g0 = accg[i][j][0], g1 = accg[i][j][1], g2 = accg[i][j][2], g3 = accg[i][j][3];
            float u0 = accu[i][j][0], u1 = accu[i][j][1], u2 = accu[i][j][2], u3 = accu[i][j][3];
            float h0 = rna_tf32((g0 / (1.f + __expf(-g0))) * u0);
            float h1 = rna_tf32((g1 / (1.f + __expf(-g1))) * u1);
            float h2 = rna_tf32((g2 / (1.f + __expf(-g2))) * u2);
            float h3 = rna_tf32((g3 / (1.f + __expf(-g3))) * u3);
            *(float2*)(g_h + (size_t)row0 * INTER + cg)       = make_float2(h0, h1);
            *(float2*)(g_h + (size_t)(row0 + 8) * INTER + cg) = make_float2(h2, h3);
        }
    }
}

// ---------------- GEMM2: out[tok] += coef * (h @ w2^T) ----------------
// CTA tile: M=128, N=256, K-chunk=32. stage: A[128x32] @0 (16KB), B[256x32] @16384 (32KB)
#define G2_STAGE  49152
#define G2_SMEMSZ (2 * G2_STAGE + 1024)

__global__ __launch_bounds__(256, 1) void gemm2_kernel(const float* __restrict__ w2,
                                                       float* __restrict__ out) {
    extern __shared__ char sm[];
    const int r0 = blockIdx.y * PADM;
    if (r0 >= g_off[NE]) return;
    int e = 0;
    #pragma unroll
    for (int i = 1; i < NE; i++) if (r0 >= g_off[i]) e = i;
    const int n0 = blockIdx.x * 256;
    const int tid = threadIdx.x, wid = tid >> 5, lane = tid & 31;
    int*   rtok  = (int*)(sm + 2 * G2_STAGE);
    float* rcoef = (float*)(sm + 2 * G2_STAGE + 512);
    if (tid < 128) { rtok[tid] = g_tok[r0 + tid]; rcoef[tid] = g_coef[r0 + tid]; }
    __syncthreads();

    const int lr = tid >> 3, lc = tid & 7;
    const uint32_t as0 = swz(lr * 128 + lc * 16);
    const float* ag[4];
    #pragma unroll
    for (int j = 0; j < 4; j++) ag[j] = g_h + (size_t)(r0 + lr + 32 * j) * INTER + lc * 4;
    const float* bb = w2 + ((size_t)e * HIDDEN + n0 + lr) * INTER + lc * 4;

    float4 pA[4], pB[8];
    auto prefetch = [&](int kc) {
        int k0 = kc * KC;
        #pragma unroll
        for (int j = 0; j < 4; j++) pA[j] = __ldg((const float4*)(ag[j] + k0));
        #pragma unroll
        for (int j = 0; j < 8; j++) pB[j] = __ldg((const float4*)(bb + (size_t)(32 * j) * INTER + k0));
    };
    auto stage_store = [&](int st) {
        char* base = sm + st * G2_STAGE;
        #pragma unroll
        for (int j = 0; j < 4; j++) *(uint4*)(base + as0 + 4096 * j)         = as_u4(pA[j]);  // g_h pre-rounded
        #pragma unroll
        for (int j = 0; j < 8; j++) *(uint4*)(base + 16384 + as0 + 4096 * j) = tf32x4(pB[j]);
    };

    const int mw = wid & 1, nw = wid >> 1;       // warp = 64M x 64N
    const int r = lane >> 2, q = lane & 3;
    float acc[4][8][4] = {};

    prefetch(0);
    const int NCk = INTER / KC;   // 128
    for (int kc = 0; kc < NCk; kc++) {
        int st = kc & 1;
        __syncthreads();
        stage_store(st);
        __syncthreads();
        if (kc + 1 < NCk) prefetch(kc + 1);
        const char* A = sm + st * G2_STAGE;
        const char* B = A + 16384;
        #pragma unroll
        for (int k8 = 0; k8 < 4; k8++) {
            uint32_t a[4][4];
            const int col = (k8 * 8 + q) * 4;
            #pragma unroll
            for (int i = 0; i < 4; i++) {
                int row = mw * 64 + i * 16 + r;
                a[i][0] = *(const uint32_t*)(A + swz(row * 128 + col));
                a[i][1] = *(const uint32_t*)(A + swz((row + 8) * 128 + col));
                a[i][2] = *(const uint32_t*)(A + swz(row * 128 + col + 16));
                a[i][3] = *(const uint32_t*)(A + swz((row + 8) * 128 + col + 16));
            }
            #pragma unroll
            for (int j = 0; j < 8; j++) {
                int nr = nw * 64 + j * 8 + r;
                uint32_t b0 = *(const uint32_t*)(B + swz(nr * 128 + col));
                uint32_t b1 = *(const uint32_t*)(B + swz(nr * 128 + col + 16));
                #pragma unroll
                for (int i = 0; i < 4; i++) mma8(acc[i][j], a[i], b0, b1);
            }
        }
    }

    // epilogue: atomic scatter with routing coefficient
    #pragma unroll
    for (int i = 0; i < 4; i++) {
        int rl = mw * 64 + i * 16 + r;
        float cf0 = rcoef[rl], cf1 = rcoef[rl + 8];
        int   tk0 = rtok[rl],  tk1 = rtok[rl + 8];
        #pragma unroll
        for (int j = 0; j < 8; j++) {
            int cg = n0 + nw * 64 + j * 8 + q * 2;
            if (cf0 != 0.f) {
                float* p = out + (size_t)tk0 * HIDDEN + cg;
                atomicAdd(p,     cf0 * acc[i][j][0]);
                atomicAdd(p + 1, cf0 * acc[i][j][1]);
            }
            if (cf1 != 0.f) {
                float* p = out + (size_t)tk1 * HIDDEN + cg;
                atomicAdd(p,     cf1 * acc[i][j][2]);
                atomicAdd(p + 1, cf1 * acc[i][j][3]);
            }
        }
    }
}

// ---------------- launch ----------------
extern "C" void kernel_launch(void* const* d_in, const int* in_sizes, int n_in,
                              void* d_out, int out_size) {
    const float* x  = (const float*)d_in[0];
    const float* gw = (const float*)d_in[1];
    const float* w1 = (const float*)d_in[2];
    const float* w2 = (const float*)d_in[3];
    const float* w3 = (const float*)d_in[4];
    float* out = (float*)d_out;

    cudaFuncSetAttribute(gemm1_kernel, cudaFuncAttributeMaxDynamicSharedMemorySize, G1_SMEMSZ);
    cudaFuncSetAttribute(gemm2_kernel, cudaFuncAttributeMaxDynamicSharedMemorySize, G2_SMEMSZ);

    cudaMemsetAsync(d_out, 0, (size_t)TOKENS * HIDDEN * sizeof(float), 0);

    zero_counts_kernel<<<1, 32>>>();
    router_kernel<<<TOKENS, 256>>>(x, gw);
    build_lists_kernel<<<NE, 256>>>();

    gemm1_kernel<<<dim3(INTER / 128, MT), 256, G1_SMEMSZ>>>(x, w1, w3);
    gemm2_kernel<<<dim3(HIDDEN / 256, MT), 256, G2_SMEMSZ>>>(w2, out);
}

// round 11
// speedup vs baseline: 1.1021x; 1.1021x over previous
#include <cuda_runtime.h>
#include <cstdint>
#include <math.h>

#define NE      8
#define HIDDEN  2048
#define INTER   4096
#define TOKENS  8192
#define SLOTS   (TOKENS * 2)
#define PADM    128
#define SLOTS_PAD (SLOTS + NE * PADM)   // 17408
#define MT      (SLOTS_PAD / PADM)      // 136
#define KC      32                      // K elems per pipeline chunk
#define XELEMS  ((size_t)TOKENS * HIDDEN)

// ---------------- scratch (device globals: allocation-free, ~352 MB total) ----------------
__device__ int   g_topk_idx[SLOTS];
__device__ float g_topk_w[SLOTS];
__device__ int   g_counts[NE];
__device__ int   g_off[NE + 1];
__device__ int   g_tok[SLOTS_PAD];
__device__ float g_coef[SLOTS_PAD];
__device__ float g_h[(size_t)SLOTS_PAD * INTER];   // ~285 MB
__device__ float g_xt[XELEMS];                     // tf32-rounded x (~67 MB)

// ---------------- helpers ----------------
__device__ __forceinline__ uint32_t smem_u32(const void* p) {
    uint32_t a;
    asm("{ .reg .u64 t; cvta.to.shared.u64 t, %1; cvt.u32.u64 %0, t; }" : "=r"(a) : "l"(p));
    return a;
}
__device__ __forceinline__ uint32_t swz(uint32_t off) { return off ^ ((off >> 3) & 0x70); }

__device__ __forceinline__ float rna_tf32(float f) {
    uint32_t r;
    asm("cvt.rna.tf32.f32 %0, %1;" : "=r"(r) : "f"(f));
    return __uint_as_float(r);
}
__device__ __forceinline__ uint4 tf32x4(float4 v) {
    uint4 r;
    asm("cvt.rna.tf32.f32 %0, %1;" : "=r"(r.x) : "f"(v.x));
    asm("cvt.rna.tf32.f32 %0, %1;" : "=r"(r.y) : "f"(v.y));
    asm("cvt.rna.tf32.f32 %0, %1;" : "=r"(r.z) : "f"(v.z));
    asm("cvt.rna.tf32.f32 %0, %1;" : "=r"(r.w) : "f"(v.w));
    return r;
}

#define CP_ASYNC16(s, g) asm volatile("cp.async.cg.shared.global [%0], [%1], 16;" :: "r"(s), "l"(g))
#define CP_COMMIT()      asm volatile("cp.async.commit_group;" ::: "memory")
#define CP_WAIT0()       asm volatile("cp.async.wait_group 0;" ::: "memory")

// m16n8k8 tf32 mma: D/C fp32, A row-major, B col-major
__device__ __forceinline__ void mma8(float* c, const uint32_t* a, uint32_t b0, uint32_t b1) {
    asm volatile(
        "mma.sync.aligned.m16n8k8.row.col.f32.tf32.tf32.f32 "
        "{%0,%1,%2,%3},{%4,%5,%6,%7},{%8,%9},{%0,%1,%2,%3};"
        : "+f"(c[0]), "+f"(c[1]), "+f"(c[2]), "+f"(c[3])
        : "r"(a[0]), "r"(a[1]), "r"(a[2]), "r"(a[3]), "r"(b0), "r"(b1));
}

// ---------------- x pre-conversion (RNA tf32) ----------------
__global__ __launch_bounds__(256) void cvt_x_kernel(const float4* __restrict__ in) {
    size_t i = (size_t)blockIdx.x * 256 + threadIdx.x;
    if (i < XELEMS / 4) {
        uint4 o = tf32x4(in[i]);
        ((float4*)g_xt)[i] = *(float4*)&o;
    }
}

// ---------------- router (with fused expert counting) ----------------
__global__ __launch_bounds__(256) void router_kernel(const float* __restrict__ x,
                                                     const float* __restrict__ gw) {
    __shared__ float xs[HIDDEN];
    __shared__ float logits[NE];
    int t = blockIdx.x, tid = threadIdx.x;
    const float* xr = x + (size_t)t * HIDDEN;
    for (int i = tid; i < HIDDEN; i += 256) xs[i] = xr[i];
    __syncthreads();
    int w = tid >> 5, lane = tid & 31;
    const float* gr = gw + (size_t)w * HIDDEN;
    float s = 0.f;
    for (int i = lane; i < HIDDEN; i += 32) s += xs[i] * gr[i];
    #pragma unroll
    for (int o = 16; o; o >>= 1) s += __shfl_xor_sync(0xffffffffu, s, o);
    if (lane == 0) logits[w] = s;
    __syncthreads();
    if (tid == 0) {
        float m = logits[0];
        #pragma unroll
        for (int e = 1; e < NE; e++) m = fmaxf(m, logits[e]);
        float p[NE]; float sum = 0.f;
        #pragma unroll
        for (int e = 0; e < NE; e++) { p[e] = __expf(logits[e] - m); sum += p[e]; }
        float inv = 1.f / sum;
        #pragma unroll
        for (int e = 0; e < NE; e++) p[e] *= inv;
        int i1 = 0;
        #pragma unroll
        for (int e = 1; e < NE; e++) if (p[e] > p[i1]) i1 = e;
        int i2 = (i1 == 0) ? 1 : 0;
        #pragma unroll
        for (int e = 0; e < NE; e++) if (e != i1 && e != i2 && p[e] > p[i2]) i2 = e;
        g_topk_idx[2 * t] = i1;     g_topk_w[2 * t] = p[i1];
        g_topk_idx[2 * t + 1] = i2; g_topk_w[2 * t + 1] = p[i2];
        atomicAdd(&g_counts[i1], 1);
        atomicAdd(&g_counts[i2], 1);
    }
}

__global__ void zero_counts_kernel() { if (threadIdx.x < NE) g_counts[threadIdx.x] = 0; }

// build lists; each block also derives the expert offsets locally
__global__ __launch_bounds__(256) void build_lists_kernel() {
    int e = blockIdx.x, tid = threadIdx.x, lane = tid & 31, wid = tid >> 5;
    __shared__ int wsum[8]; __shared__ int sbase; __shared__ int seg_end;
    if (tid == 0) {
        int o = 0, my = 0, tot = 0;
        #pragma unroll
        for (int i = 0; i < NE; i++) {
            int pad = ((g_counts[i] + PADM - 1) / PADM) * PADM;
            if (i == e) my = o;
            o += pad;
            if (i == e) tot = o;
        }
        sbase = my;
        seg_end = tot;
        g_off[e] = my;
        if (e == NE - 1) g_off[NE] = o;
    }
    __syncthreads();
    int seg0 = sbase, segend = seg_end;
    for (int base = 0; base < TOKENS; base += 256) {
        int t = base + tid; int match = 0; float c = 0.f;
        int i0 = g_topk_idx[2 * t], i1 = g_topk_idx[2 * t + 1];
        if (i0 == e) { match = 1; c = g_topk_w[2 * t]; }
        else if (i1 == e) { match = 1; c = g_topk_w[2 * t + 1]; }
        unsigned m = __ballot_sync(0xffffffffu, match);
        if (lane == 0) wsum[wid] = __popc(m);
        __syncthreads();
        int woff = 0, tot = 0;
        #pragma unroll
        for (int i = 0; i < 8; i++) { int v = wsum[i]; if (i < wid) woff += v; tot += v; }
        if (match) { int p = sbase + woff + __popc(m & ((1u << lane) - 1)); g_tok[p] = t; g_coef[p] = c; }
        __syncthreads();
        if (tid == 0) sbase += tot;
        __syncthreads();
    }
    for (int p = seg0 + g_counts[e] + tid; p < segend; p += 256) { g_tok[p] = 0; g_coef[p] = 0.f; }
}

// ---------------- GEMM1: g_h = silu(x@w1^T) * (x@w3^T) ----------------
// CTA tile: M=128, N=128 (each of w1,w3). Stage 48KB: A@0 (cp.async from g_xt),
// B1@16384, B3@32768 (LDG->cvt->STS). One sync/chunk; STS overlaps MMA.
#define G1_STAGE  49152
#define G1_SMEMSZ (2 * G1_STAGE + 512)

__global__ __launch_bounds__(256, 1) void gemm1_kernel(const float* __restrict__ w1,
                                                       const float* __restrict__ w3) {
    extern __shared__ char sm[];
    const int r0 = blockIdx.y * PADM;
    if (r0 >= g_off[NE]) return;
    int e = 0;
    #pragma unroll
    for (int i = 1; i < NE; i++) if (r0 >= g_off[i]) e = i;
    const int n0 = blockIdx.x * 128;
    const int tid = threadIdx.x, wid = tid >> 5, lane = tid & 31;
    const uint32_t sb = smem_u32(sm);
    int* rtok = (int*)(sm + 2 * G1_STAGE);
    if (tid < 128) rtok[tid] = g_tok[r0 + tid];
    __syncthreads();

    const int lr = tid >> 3, lc = tid & 7;
    const uint32_t as0 = swz(lr * 128 + lc * 16);
    const float* agx[4];
    #pragma unroll
    for (int j = 0; j < 4; j++) agx[j] = g_xt + (size_t)rtok[lr + 32 * j] * HIDDEN + lc * 4;
    const float* b1b = w1 + ((size_t)e * INTER + n0 + lr) * HIDDEN + lc * 4;
    const float* b3b = w3 + ((size_t)e * INTER + n0 + lr) * HIDDEN + lc * 4;

    float4 pB1[4], pB3[4];
    auto issueA = [&](int st, int kc) {
        uint32_t base = sb + st * G1_STAGE;
        int k0 = kc * KC;
        #pragma unroll
        for (int j = 0; j < 4; j++) CP_ASYNC16(base + as0 + 4096 * j, agx[j] + k0);
    };
    auto ldgB = [&](int kc) {
        int k0 = kc * KC;
        #pragma unroll
        for (int j = 0; j < 4; j++) pB1[j] = __ldg((const float4*)(b1b + (size_t)(32 * j) * HIDDEN + k0));
        #pragma unroll
        for (int j = 0; j < 4; j++) pB3[j] = __ldg((const float4*)(b3b + (size_t)(32 * j) * HIDDEN + k0));
    };
    auto stsB = [&](int st) {
        char* base = sm + st * G1_STAGE;
        #pragma unroll
        for (int j = 0; j < 4; j++) *(uint4*)(base + 16384 + as0 + 4096 * j) = tf32x4(pB1[j]);
        #pragma unroll
        for (int j = 0; j < 4; j++) *(uint4*)(base + 32768 + as0 + 4096 * j) = tf32x4(pB3[j]);
    };

    const int mw = wid & 1, nw = wid >> 1;       // warp = 64M x 32N (per matrix)
    const int r = lane >> 2, q = lane & 3;
    float accg[4][4][4] = {}, accu[4][4][4] = {};

    // prologue: A(0) async; B(0) via regs -> STS; LDG B(1)
    issueA(0, 0); CP_COMMIT();
    ldgB(0);
    stsB(0);
    ldgB(1);

    const int NCk = HIDDEN / KC;   // 64
    for (int kc = 0; kc < NCk; kc++) {
        const int st = kc & 1;
        CP_WAIT0();                // A(st) landed (issued one chunk ago)
        __syncthreads();           // B(st) visible; both stages free of readers
        if (kc + 1 < NCk) {
            stsB(st ^ 1);          // kc+1 weights (regs ready) — overlaps MMA below
            issueA(st ^ 1, kc + 1); CP_COMMIT();
        }
        if (kc + 2 < NCk) ldgB(kc + 2);
        const char* A  = sm + st * G1_STAGE;
        const char* B1 = A + 16384;
        const char* B3 = A + 32768;
        #pragma unroll
        for (int k8 = 0; k8 < 4; k8++) {
            uint32_t a[4][4];
            const int col = (k8 * 8 + q) * 4;
            #pragma unroll
            for (int i = 0; i < 4; i++) {
                int row = mw * 64 + i * 16 + r;
                a[i][0] = *(const uint32_t*)(A + swz(row * 128 + col));
                a[i][1] = *(const uint32_t*)(A + swz((row + 8) * 128 + col));
                a[i][2] = *(const uint32_t*)(A + swz(row * 128 + col + 16));
                a[i][3] = *(const uint32_t*)(A + swz((row + 8) * 128 + col + 16));
            }
            #pragma unroll
            for (int j = 0; j < 4; j++) {
                int nr = nw * 32 + j * 8 + r;
                uint32_t b1a = *(const uint32_t*)(B1 + swz(nr * 128 + col));
                uint32_t b1c = *(const uint32_t*)(B1 + swz(nr * 128 + col + 16));
                uint32_t b3a = *(const uint32_t*)(B3 + swz(nr * 128 + col));
                uint32_t b3c = *(const uint32_t*)(B3 + swz(nr * 128 + col + 16));
                #pragma unroll
                for (int i = 0; i < 4; i++) {
                    mma8(accg[i][j], a[i], b1a, b1c);
                    mma8(accu[i][j], a[i], b3a, b3c);
                }
            }
        }
    }

    // epilogue: h = rna(silu(g) * u), stored tf32-rounded for gemm2
    #pragma unroll
    for (int i = 0; i < 4; i++) {
        int row0 = r0 + mw * 64 + i * 16 + r;
        #pragma unroll
        for (int j = 0; j < 4; j++) {
            int cg = n0 + nw * 32 + j * 8 + q * 2;
            float g0 = accg[i][j][0], g1 = accg[i][j][1], g2 = accg[i][j][2], g3 = accg[i][j][3];
            float u0 = accu[i][j][0], u1 = accu[i][j][1], u2 = accu[i][j][2], u3 = accu[i][j][3];
            float h0 = rna_tf32((g0 / (1.f + __expf(-g0))) * u0);
            float h1 = rna_tf32((g1 / (1.f + __expf(-g1))) * u1);
            float h2 = rna_tf32((g2 / (1.f + __expf(-g2))) * u2);
            float h3 = rna_tf32((g3 / (1.f + __expf(-g3))) * u3);
            *(float2*)(g_h + (size_t)row0 * INTER + cg)       = make_float2(h0, h1);
            *(float2*)(g_h + (size_t)(row0 + 8) * INTER + cg) = make_float2(h2, h3);
        }
    }
}

// ---------------- GEMM2: out[tok] += coef * (h @ w2^T) ----------------
// CTA tile: M=128, N=256. Stage 48KB: A@0 (cp.async from g_h), B@16384 (LDG->cvt->STS).
#define G2_STAGE  49152
#define G2_SMEMSZ (2 * G2_STAGE + 1024)

__global__ __launch_bounds__(256, 1) void gemm2_kernel(const float* __restrict__ w2,
                                                       float* __restrict__ out) {
    extern __shared__ char sm[];
    const int r0 = blockIdx.y * PADM;
    if (r0 >= g_off[NE]) return;
    int e = 0;
    #pragma unroll
    for (int i = 1; i < NE; i++) if (r0 >= g_off[i]) e = i;
    const int n0 = blockIdx.x * 256;
    const int tid = threadIdx.x, wid = tid >> 5, lane = tid & 31;
    const uint32_t sb = smem_u32(sm);
    int*   rtok  = (int*)(sm + 2 * G2_STAGE);
    float* rcoef = (float*)(sm + 2 * G2_STAGE + 512);
    if (tid < 128) { rtok[tid] = g_tok[r0 + tid]; rcoef[tid] = g_coef[r0 + tid]; }
    __syncthreads();

    const int lr = tid >> 3, lc = tid & 7;
    const uint32_t as0 = swz(lr * 128 + lc * 16);
    const float* ah[4];
    #pragma unroll
    for (int j = 0; j < 4; j++) ah[j] = g_h + (size_t)(r0 + lr + 32 * j) * INTER + lc * 4;
    const float* bb = w2 + ((size_t)e * HIDDEN + n0 + lr) * INTER + lc * 4;

    float4 pB[8];
    auto issueA = [&](int st, int kc) {
        uint32_t base = sb + st * G2_STAGE;
        int k0 = kc * KC;
        #pragma unroll
        for (int j = 0; j < 4; j++) CP_ASYNC16(base + as0 + 4096 * j, ah[j] + k0);
    };
    auto ldgB = [&](int kc) {
        int k0 = kc * KC;
        #pragma unroll
        for (int j = 0; j < 8; j++) pB[j] = __ldg((const float4*)(bb + (size_t)(32 * j) * INTER + k0));
    };
    auto stsB = [&](int st) {
        char* base = sm + st * G2_STAGE;
        #pragma unroll
        for (int j = 0; j < 8; j++) *(uint4*)(base + 16384 + as0 + 4096 * j) = tf32x4(pB[j]);
    };

    const int mw = wid & 1, nw = wid >> 1;       // warp = 64M x 64N
    const int r = lane >> 2, q = lane & 3;
    float acc[4][8][4] = {};

    issueA(0, 0); CP_COMMIT();
    ldgB(0);
    stsB(0);
    ldgB(1);

    const int NCk = INTER / KC;   // 128
    for (int kc = 0; kc < NCk; kc++) {
        const int st = kc & 1;
        CP_WAIT0();
        __syncthreads();
        if (kc + 1 < NCk) {
            stsB(st ^ 1);
            issueA(st ^ 1, kc + 1); CP_COMMIT();
        }
        if (kc + 2 < NCk) ldgB(kc + 2);
        const char* A = sm + st * G2_STAGE;
        const char* B = A + 16384;
        #pragma unroll
        for (int k8 = 0; k8 < 4; k8++) {
            uint32_t a[4][4];
            const int col = (k8 * 8 + q) * 4;
            #pragma unroll
            for (int i = 0; i < 4; i++) {
                int row = mw * 64 + i * 16 + r;
                a[i][0] = *(const uint32_t*)(A + swz(row * 128 + col));
                a[i][1] = *(const uint32_t*)(A + swz((row + 8) * 128 + col));
                a[i][2] = *(const uint32_t*)(A + swz(row * 128 + col + 16));
                a[i][3] = *(const uint32_t*)(A + swz((row + 8) * 128 + col + 16));
            }
            #pragma unroll
            for (int j = 0; j < 8; j++) {
                int nr = nw * 64 + j * 8 + r;
                uint32_t b0 = *(const uint32_t*)(B + swz(nr * 128 + col));
                uint32_t b1 = *(const uint32_t*)(B + swz(nr * 128 + col + 16));
                #pragma unroll
                for (int i = 0; i < 4; i++) mma8(acc[i][j], a[i], b0, b1);
            }
        }
    }

    // epilogue: atomic scatter with routing coefficient
    #pragma unroll
    for (int i = 0; i < 4; i++) {
        int rl = mw * 64 + i * 16 + r;
        float cf0 = rcoef[rl], cf1 = rcoef[rl + 8];
        int   tk0 = rtok[rl],  tk1 = rtok[rl + 8];
        #pragma unroll
        for (int j = 0; j < 8; j++) {
            int cg = n0 + nw * 64 + j * 8 + q * 2;
            if (cf0 != 0.f) {
                float* p = out + (size_t)tk0 * HIDDEN + cg;
                atomicAdd(p,     cf0 * acc[i][j][0]);
                atomicAdd(p + 1, cf0 * acc[i][j][1]);
            }
            if (cf1 != 0.f) {
                float* p = out + (size_t)tk1 * HIDDEN + cg;
                atomicAdd(p,     cf1 * acc[i][j][2]);
                atomicAdd(p + 1, cf1 * acc[i][j][3]);
            }
        }
    }
}

// ---------------- launch ----------------
extern "C" void kernel_launch(void* const* d_in, const int* in_sizes, int n_in,
                              void* d_out, int out_size) {
    const float* x  = (const float*)d_in[0];
    const float* gw = (const float*)d_in[1];
    const float* w1 = (const float*)d_in[2];
    const float* w2 = (const float*)d_in[3];
    const float* w3 = (const float*)d_in[4];
    float* out = (float*)d_out;

    cudaFuncSetAttribute(gemm1_kernel, cudaFuncAttributeMaxDynamicSharedMemorySize, G1_SMEMSZ);
    cudaFuncSetAttribute(gemm2_kernel, cudaFuncAttributeMaxDynamicSharedMemorySize, G2_SMEMSZ);

    cudaMemsetAsync(d_out, 0, (size_t)TOKENS * HIDDEN * sizeof(float), 0);

    zero_counts_kernel<<<1, 32>>>();
    cvt_x_kernel<<<(unsigned)(XELEMS / 4 / 256), 256>>>((const float4*)x);
    router_kernel<<<TOKENS, 256>>>(x, gw);
    build_lists_kernel<<<NE, 256>>>();

    gemm1_kernel<<<dim3(INTER / 128, MT), 256, G1_SMEMSZ>>>(w1, w3);
    gemm2_kernel<<<dim3(HIDDEN / 256, MT), 256, G2_SMEMSZ>>>(w2, out);
}

// round 12
// speedup vs baseline: 1.2762x; 1.1581x over previous
#include <cuda_runtime.h>
#include <cstdint>
#include <math.h>

#define NE      8
#define HIDDEN  2048
#define INTER   4096
#define TOKENS  8192
#define SLOTS   (TOKENS * 2)
#define PADM    128
#define SLOTS_PAD (SLOTS + NE * PADM)   // 17408
#define MT      (SLOTS_PAD / PADM)      // 136
#define KC      32                      // K elems per pipeline chunk
#define XELEMS  ((size_t)TOKENS * HIDDEN)

// ---------------- scratch (device globals: allocation-free, ~352 MB total) ----------------
__device__ int   g_topk_idx[SLOTS];
__device__ float g_topk_w[SLOTS];
__device__ int   g_counts[NE];
__device__ int   g_off[NE + 1];
__device__ int   g_tok[SLOTS_PAD];
__device__ float g_coef[SLOTS_PAD];
__device__ float g_h[(size_t)SLOTS_PAD * INTER];   // ~285 MB
__device__ float g_xt[XELEMS];                     // tf32-rounded x (~67 MB)

// ---------------- helpers ----------------
__device__ __forceinline__ uint32_t smem_u32(const void* p) {
    uint32_t a;
    asm("{ .reg .u64 t; cvta.to.shared.u64 t, %1; cvt.u32.u64 %0, t; }" : "=r"(a) : "l"(p));
    return a;
}
__device__ __forceinline__ uint32_t swz(uint32_t off) { return off ^ ((off >> 3) & 0x70); }

__device__ __forceinline__ float rna_tf32(float f) {
    uint32_t r;
    asm("cvt.rna.tf32.f32 %0, %1;" : "=r"(r) : "f"(f));
    return __uint_as_float(r);
}
__device__ __forceinline__ uint32_t cvt_frag(uint32_t raw) {
    uint32_t r;
    asm("cvt.rna.tf32.f32 %0, %1;" : "=r"(r) : "f"(__uint_as_float(raw)));
    return r;
}
__device__ __forceinline__ uint4 tf32x4(float4 v) {
    uint4 r;
    asm("cvt.rna.tf32.f32 %0, %1;" : "=r"(r.x) : "f"(v.x));
    asm("cvt.rna.tf32.f32 %0, %1;" : "=r"(r.y) : "f"(v.y));
    asm("cvt.rna.tf32.f32 %0, %1;" : "=r"(r.z) : "f"(v.z));
    asm("cvt.rna.tf32.f32 %0, %1;" : "=r"(r.w) : "f"(v.w));
    return r;
}

#define CP_ASYNC16(s, g) asm volatile("cp.async.cg.shared.global [%0], [%1], 16;" :: "r"(s), "l"(g))
#define CP_COMMIT()      asm volatile("cp.async.commit_group;" ::: "memory")
#define CP_WAIT1()       asm volatile("cp.async.wait_group 1;" ::: "memory")

// m16n8k8 tf32 mma: D/C fp32, A row-major, B col-major
__device__ __forceinline__ void mma8(float* c, const uint32_t* a, uint32_t b0, uint32_t b1) {
    asm volatile(
        "mma.sync.aligned.m16n8k8.row.col.f32.tf32.tf32.f32 "
        "{%0,%1,%2,%3},{%4,%5,%6,%7},{%8,%9},{%0,%1,%2,%3};"
        : "+f"(c[0]), "+f"(c[1]), "+f"(c[2]), "+f"(c[3])
        : "r"(a[0]), "r"(a[1]), "r"(a[2]), "r"(a[3]), "r"(b0), "r"(b1));
}

// ---------------- x pre-conversion (RNA tf32), fused counts zeroing ----------------
__global__ __launch_bounds__(256) void cvt_x_kernel(const float4* __restrict__ in) {
    if (blockIdx.x == 0 && threadIdx.x < NE) g_counts[threadIdx.x] = 0;
    size_t i = (size_t)blockIdx.x * 256 + threadIdx.x;
    if (i < XELEMS / 4) {
        uint4 o = tf32x4(in[i]);
        ((float4*)g_xt)[i] = *(float4*)&o;
    }
}

// ---------------- router (with fused expert counting) ----------------
__global__ __launch_bounds__(256) void router_kernel(const float* __restrict__ x,
                                                     const float* __restrict__ gw) {
    __shared__ float xs[HIDDEN];
    __shared__ float logits[NE];
    int t = blockIdx.x, tid = threadIdx.x;
    const float* xr = x + (size_t)t * HIDDEN;
    for (int i = tid; i < HIDDEN; i += 256) xs[i] = xr[i];
    __syncthreads();
    int w = tid >> 5, lane = tid & 31;
    const float* gr = gw + (size_t)w * HIDDEN;
    float s = 0.f;
    for (int i = lane; i < HIDDEN; i += 32) s += xs[i] * gr[i];
    #pragma unroll
    for (int o = 16; o; o >>= 1) s += __shfl_xor_sync(0xffffffffu, s, o);
    if (lane == 0) logits[w] = s;
    __syncthreads();
    if (tid == 0) {
        float m = logits[0];
        #pragma unroll
        for (int e = 1; e < NE; e++) m = fmaxf(m, logits[e]);
        float p[NE]; float sum = 0.f;
        #pragma unroll
        for (int e = 0; e < NE; e++) { p[e] = __expf(logits[e] - m); sum += p[e]; }
        float inv = 1.f / sum;
        #pragma unroll
        for (int e = 0; e < NE; e++) p[e] *= inv;
        int i1 = 0;
        #pragma unroll
        for (int e = 1; e < NE; e++) if (p[e] > p[i1]) i1 = e;
        int i2 = (i1 == 0) ? 1 : 0;
        #pragma unroll
        for (int e = 0; e < NE; e++) if (e != i1 && e != i2 && p[e] > p[i2]) i2 = e;
        g_topk_idx[2 * t] = i1;     g_topk_w[2 * t] = p[i1];
        g_topk_idx[2 * t + 1] = i2; g_topk_w[2 * t + 1] = p[i2];
        atomicAdd(&g_counts[i1], 1);
        atomicAdd(&g_counts[i2], 1);
    }
}

// build lists; each block also derives the expert offsets locally
__global__ __launch_bounds__(256) void build_lists_kernel() {
    int e = blockIdx.x, tid = threadIdx.x, lane = tid & 31, wid = tid >> 5;
    __shared__ int wsum[8]; __shared__ int sbase; __shared__ int seg_end;
    if (tid == 0) {
        int o = 0, my = 0, tot = 0;
        #pragma unroll
        for (int i = 0; i < NE; i++) {
            int pad = ((g_counts[i] + PADM - 1) / PADM) * PADM;
            if (i == e) my = o;
            o += pad;
            if (i == e) tot = o;
        }
        sbase = my;
        seg_end = tot;
        g_off[e] = my;
        if (e == NE - 1) g_off[NE] = o;
    }
    __syncthreads();
    int seg0 = sbase, segend = seg_end;
    for (int base = 0; base < TOKENS; base += 256) {
        int t = base + tid; int match = 0; float c = 0.f;
        int i0 = g_topk_idx[2 * t], i1 = g_topk_idx[2 * t + 1];
        if (i0 == e) { match = 1; c = g_topk_w[2 * t]; }
        else if (i1 == e) { match = 1; c = g_topk_w[2 * t + 1]; }
        unsigned m = __ballot_sync(0xffffffffu, match);
        if (lane == 0) wsum[wid] = __popc(m);
        __syncthreads();
        int woff = 0, tot = 0;
        #pragma unroll
        for (int i = 0; i < 8; i++) { int v = wsum[i]; if (i < wid) woff += v; tot += v; }
        if (match) { int p = sbase + woff + __popc(m & ((1u << lane) - 1)); g_tok[p] = t; g_coef[p] = c; }
        __syncthreads();
        if (tid == 0) sbase += tot;
        __syncthreads();
    }
    for (int p = seg0 + g_counts[e] + tid; p < segend; p += 256) { g_tok[p] = 0; g_coef[p] = 0.f; }
}

// ---------------- GEMM1: g_h = silu(x@w1^T) * (x@w3^T) ----------------
// CTA tile: M=128, N=128 (each of w1,w3). 3-stage cp.async pipeline, all operands async.
// stage 48KB: A@0 (pre-rounded g_xt), B1@16384 (raw fp32), B3@32768 (raw fp32).
// B fragments converted to tf32 (RNA) after LDS.
#define G1_STAGE  49152
#define G1_SMEMSZ (3 * G1_STAGE + 512)

__global__ __launch_bounds__(256, 1) void gemm1_kernel(const float* __restrict__ w1,
                                                       const float* __restrict__ w3) {
    extern __shared__ char sm[];
    const int r0 = blockIdx.y * PADM;
    if (r0 >= g_off[NE]) return;
    int e = 0;
    #pragma unroll
    for (int i = 1; i < NE; i++) if (r0 >= g_off[i]) e = i;
    const int n0 = blockIdx.x * 128;
    const int tid = threadIdx.x, wid = tid >> 5, lane = tid & 31;
    const uint32_t sb = smem_u32(sm);
    int* rtok = (int*)(sm + 3 * G1_STAGE);
    if (tid < 128) rtok[tid] = g_tok[r0 + tid];
    __syncthreads();

    const int lr = tid >> 3, lc = tid & 7;
    const uint32_t as0 = swz(lr * 128 + lc * 16);
    const float* agx[4];
    #pragma unroll
    for (int j = 0; j < 4; j++) agx[j] = g_xt + (size_t)rtok[lr + 32 * j] * HIDDEN + lc * 4;
    const float* b1g = w1 + ((size_t)e * INTER + n0 + lr) * HIDDEN + lc * 4;
    const float* b3g = w3 + ((size_t)e * INTER + n0 + lr) * HIDDEN + lc * 4;

    auto issueStage = [&](int st, int kc) {
        uint32_t base = sb + st * G1_STAGE;
        int k0 = kc * KC;
        #pragma unroll
        for (int j = 0; j < 4; j++) CP_ASYNC16(base + as0 + 4096 * j, agx[j] + k0);
        #pragma unroll
        for (int j = 0; j < 4; j++) CP_ASYNC16(base + 16384 + as0 + 4096 * j, b1g + (size_t)(32 * j) * HIDDEN + k0);
        #pragma unroll
        for (int j = 0; j < 4; j++) CP_ASYNC16(base + 32768 + as0 + 4096 * j, b3g + (size_t)(32 * j) * HIDDEN + k0);
    };

    const int mw = wid & 1, nw = wid >> 1;       // warp = 64M x 32N (per matrix)
    const int r = lane >> 2, q = lane & 3;
    float accg[4][4][4] = {}, accu[4][4][4] = {};

    issueStage(0, 0); CP_COMMIT();
    issueStage(1, 1); CP_COMMIT();

    const int NCk = HIDDEN / KC;   // 64
    for (int kc = 0; kc < NCk; kc++) {
        const int st = kc % 3;
        CP_WAIT1();                // stage kc landed (committed 2 groups ago)
        __syncthreads();           // all threads' copies visible; slot (kc+2)%3 free
        if (kc + 2 < NCk) issueStage((kc + 2) % 3, kc + 2);
        CP_COMMIT();               // uniform group accounting (empty at tail)
        const char* A  = sm + st * G1_STAGE;
        const char* B1 = A + 16384;
        const char* B3 = A + 32768;
        #pragma unroll
        for (int k8 = 0; k8 < 4; k8++) {
            uint32_t a[4][4];
            const int col = (k8 * 8 + q) * 4;
            #pragma unroll
            for (int i = 0; i < 4; i++) {
                int row = mw * 64 + i * 16 + r;
                a[i][0] = *(const uint32_t*)(A + swz(row * 128 + col));
                a[i][1] = *(const uint32_t*)(A + swz((row + 8) * 128 + col));
                a[i][2] = *(const uint32_t*)(A + swz(row * 128 + col + 16));
                a[i][3] = *(const uint32_t*)(A + swz((row + 8) * 128 + col + 16));
            }
            #pragma unroll
            for (int j = 0; j < 4; j++) {
                int nr = nw * 32 + j * 8 + r;
                uint32_t b1a = cvt_frag(*(const uint32_t*)(B1 + swz(nr * 128 + col)));
                uint32_t b1c = cvt_frag(*(const uint32_t*)(B1 + swz(nr * 128 + col + 16)));
                uint32_t b3a = cvt_frag(*(const uint32_t*)(B3 + swz(nr * 128 + col)));
                uint32_t b3c = cvt_frag(*(const uint32_t*)(B3 + swz(nr * 128 + col + 16)));
                #pragma unroll
                for (int i = 0; i < 4; i++) {
                    mma8(accg[i][j], a[i], b1a, b1c);
                    mma8(accu[i][j], a[i], b3a, b3c);
                }
            }
        }
    }

    // epilogue: h = rna(silu(g) * u), stored tf32-rounded for gemm2
    #pragma unroll
    for (int i = 0; i < 4; i++) {
        int row0 = r0 + mw * 64 + i * 16 + r;
        #pragma unroll
        for (int j = 0; j < 4; j++) {
            int cg = n0 + nw * 32 + j * 8 + q * 2;
            float g0 = accg[i][j][0], g1 = accg[i][j][1], g2 = accg[i][j][2], g3 = accg[i][j][3];
            float u0 = accu[i][j][0], u1 = accu[i][j][1], u2 = accu[i][j][2], u3 = accu[i][j][3];
            float h0 = rna_tf32((g0 / (1.f + __expf(-g0))) * u0);
            float h1 = rna_tf32((g1 / (1.f + __expf(-g1))) * u1);
            float h2 = rna_tf32((g2 / (1.f + __expf(-g2))) * u2);
            float h3 = rna_tf32((g3 / (1.f + __expf(-g3))) * u3);
            *(float2*)(g_h + (size_t)row0 * INTER + cg)       = make_float2(h0, h1);
            *(float2*)(g_h + (size_t)(row0 + 8) * INTER + cg) = make_float2(h2, h3);
        }
    }
}

// ---------------- GEMM2: out[tok] += coef * (h @ w2^T) ----------------
// CTA tile: M=128, N=256. 3-stage cp.async. Stage 48KB: A@0 (g_h, pre-rounded),
// B@16384 (raw fp32 w2, fragment-converted).
#define G2_STAGE  49152
#define G2_SMEMSZ (3 * G2_STAGE + 1024)

__global__ __launch_bounds__(256, 1) void gemm2_kernel(const float* __restrict__ w2,
                                                       float* __restrict__ out) {
    extern __shared__ char sm[];
    const int r0 = blockIdx.y * PADM;
    if (r0 >= g_off[NE]) return;
    int e = 0;
    #pragma unroll
    for (int i = 1; i < NE; i++) if (r0 >= g_off[i]) e = i;
    const int n0 = blockIdx.x * 256;
    const int tid = threadIdx.x, wid = tid >> 5, lane = tid & 31;
    const uint32_t sb = smem_u32(sm);
    int*   rtok  = (int*)(sm + 3 * G2_STAGE);
    float* rcoef = (float*)(sm + 3 * G2_STAGE + 512);
    if (tid < 128) { rtok[tid] = g_tok[r0 + tid]; rcoef[tid] = g_coef[r0 + tid]; }
    __syncthreads();

    const int lr = tid >> 3, lc = tid & 7;
    const uint32_t as0 = swz(lr * 128 + lc * 16);
    const float* ah[4];
    #pragma unroll
    for (int j = 0; j < 4; j++) ah[j] = g_h + (size_t)(r0 + lr + 32 * j) * INTER + lc * 4;
    const float* bg = w2 + ((size_t)e * HIDDEN + n0 + lr) * INTER + lc * 4;

    auto issueStage = [&](int st, int kc) {
        uint32_t base = sb + st * G2_STAGE;
        int k0 = kc * KC;
        #pragma unroll
        for (int j = 0; j < 4; j++) CP_ASYNC16(base + as0 + 4096 * j, ah[j] + k0);
        #pragma unroll
        for (int j = 0; j < 8; j++) CP_ASYNC16(base + 16384 + as0 + 4096 * j, bg + (size_t)(32 * j) * INTER + k0);
    };

    const int mw = wid & 1, nw = wid >> 1;       // warp = 64M x 64N
    const int r = lane >> 2, q = lane & 3;
    float acc[4][8][4] = {};

    issueStage(0, 0); CP_COMMIT();
    issueStage(1, 1); CP_COMMIT();

    const int NCk = INTER / KC;   // 128
    for (int kc = 0; kc < NCk; kc++) {
        const int st = kc % 3;
        CP_WAIT1();
        __syncthreads();
        if (kc + 2 < NCk) issueStage((kc + 2) % 3, kc + 2);
        CP_COMMIT();
        const char* A = sm + st * G2_STAGE;
        const char* B = A + 16384;
        #pragma unroll
        for (int k8 = 0; k8 < 4; k8++) {
            uint32_t a[4][4];
            const int col = (k8 * 8 + q) * 4;
            #pragma unroll
            for (int i = 0; i < 4; i++) {
                int row = mw * 64 + i * 16 + r;
                a[i][0] = *(const uint32_t*)(A + swz(row * 128 + col));
                a[i][1] = *(const uint32_t*)(A + swz((row + 8) * 128 + col));
                a[i][2] = *(const uint32_t*)(A + swz(row * 128 + col + 16));
                a[i][3] = *(const uint32_t*)(A + swz((row + 8) * 128 + col + 16));
            }
            #pragma unroll
            for (int j = 0; j < 8; j++) {
                int nr = nw * 64 + j * 8 + r;
                uint32_t b0 = cvt_frag(*(const uint32_t*)(B + swz(nr * 128 + col)));
                uint32_t b1 = cvt_frag(*(const uint32_t*)(B + swz(nr * 128 + col + 16)));
                #pragma unroll
                for (int i = 0; i < 4; i++) mma8(acc[i][j], a[i], b0, b1);
            }
        }
    }

    // epilogue: atomic scatter with routing coefficient
    #pragma unroll
    for (int i = 0; i < 4; i++) {
        int rl = mw * 64 + i * 16 + r;
        float cf0 = rcoef[rl], cf1 = rcoef[rl + 8];
        int   tk0 = rtok[rl],  tk1 = rtok[rl + 8];
        #pragma unroll
        for (int j = 0; j < 8; j++) {
            int cg = n0 + nw * 64 + j * 8 + q * 2;
            if (cf0 != 0.f) {
                float* p = out + (size_t)tk0 * HIDDEN + cg;
                atomicAdd(p,     cf0 * acc[i][j][0]);
                atomicAdd(p + 1, cf0 * acc[i][j][1]);
            }
            if (cf1 != 0.f) {
                float* p = out + (size_t)tk1 * HIDDEN + cg;
                atomicAdd(p,     cf1 * acc[i][j][2]);
                atomicAdd(p + 1, cf1 * acc[i][j][3]);
            }
        }
    }
}

// ---------------- launch ----------------
extern "C" void kernel_launch(void* const* d_in, const int* in_sizes, int n_in,
                              void* d_out, int out_size) {
    const float* x  = (const float*)d_in[0];
    const float* gw = (const float*)d_in[1];
    const float* w1 = (const float*)d_in[2];
    const float* w2 = (const float*)d_in[3];
    const float* w3 = (const float*)d_in[4];
    float* out = (float*)d_out;

    cudaFuncSetAttribute(gemm1_kernel, cudaFuncAttributeMaxDynamicSharedMemorySize, G1_SMEMSZ);
    cudaFuncSetAttribute(gemm2_kernel, cudaFuncAttributeMaxDynamicSharedMemorySize, G2_SMEMSZ);

    // launch order chosen so gemm1 is the 5th launch (ncu -s 5 -c 1 capture slot)
    cudaMemsetAsync(d_out, 0, (size_t)TOKENS * HIDDEN * sizeof(float), 0);   // 1
    cvt_x_kernel<<<(unsigned)(XELEMS / 4 / 256), 256>>>((const float4*)x);   // 2 (zeroes g_counts too)
    router_kernel<<<TOKENS, 256>>>(x, gw);                                   // 3
    build_lists_kernel<<<NE, 256>>>();                                       // 4
    gemm1_kernel<<<dim3(INTER / 128, MT), 256, G1_SMEMSZ>>>(w1, w3);         // 5 <- profiled
    gemm2_kernel<<<dim3(HIDDEN / 256, MT), 256, G2_SMEMSZ>>>(w2, out);       // 6
}

// round 13
// speedup vs baseline: 1.4979x; 1.1737x over previous
#include <cuda_runtime.h>
#include <cstdint>
#include <math.h>

#define NE      8
#define HIDDEN  2048
#define INTER   4096
#define TOKENS  8192
#define SLOTS   (TOKENS * 2)
#define PADM    128
#define SLOTS_PAD (SLOTS + NE * PADM)   // 17408
#define MT      (SLOTS_PAD / PADM)      // 136
#define KC      32                      // K elems per pipeline chunk
#define XELEMS  ((size_t)TOKENS * HIDDEN)

// ---------------- scratch (device globals: allocation-free, ~352 MB total) ----------------
__device__ int   g_topk_idx[SLOTS];
__device__ float g_topk_w[SLOTS];
__device__ int   g_counts[NE];
__device__ int   g_off[NE + 1];
__device__ int   g_tok[SLOTS_PAD];
__device__ float g_coef[SLOTS_PAD];
__device__ float g_h[(size_t)SLOTS_PAD * INTER];   // ~285 MB
__device__ float g_xt[XELEMS];                     // tf32-rounded x (~67 MB)

// ---------------- helpers ----------------
__device__ __forceinline__ uint32_t smem_u32(const void* p) {
    uint32_t a;
    asm("{ .reg .u64 t; cvta.to.shared.u64 t, %1; cvt.u32.u64 %0, t; }" : "=r"(a) : "l"(p));
    return a;
}
__device__ __forceinline__ uint32_t swz(uint32_t off) { return off ^ ((off >> 3) & 0x70); }

__device__ __forceinline__ float rna_tf32(float f) {
    uint32_t r;
    asm("cvt.rna.tf32.f32 %0, %1;" : "=r"(r) : "f"(f));
    return __uint_as_float(r);
}
__device__ __forceinline__ uint32_t cvt_frag(uint32_t raw) {
    uint32_t r;
    asm("cvt.rna.tf32.f32 %0, %1;" : "=r"(r) : "f"(__uint_as_float(raw)));
    return r;
}
__device__ __forceinline__ uint4 tf32x4(float4 v) {
    uint4 r;
    asm("cvt.rna.tf32.f32 %0, %1;" : "=r"(r.x) : "f"(v.x));
    asm("cvt.rna.tf32.f32 %0, %1;" : "=r"(r.y) : "f"(v.y));
    asm("cvt.rna.tf32.f32 %0, %1;" : "=r"(r.z) : "f"(v.z));
    asm("cvt.rna.tf32.f32 %0, %1;" : "=r"(r.w) : "f"(v.w));
    return r;
}

#define CP_ASYNC16(s, g) asm volatile("cp.async.cg.shared.global [%0], [%1], 16;" :: "r"(s), "l"(g))
#define CP_COMMIT()      asm volatile("cp.async.commit_group;" ::: "memory")
#define CP_WAIT1()       asm volatile("cp.async.wait_group 1;" ::: "memory")

// m16n8k8 tf32 mma: D/C fp32, A row-major, B col-major
__device__ __forceinline__ void mma8(float* c, const uint32_t* a, uint32_t b0, uint32_t b1) {
    asm volatile(
        "mma.sync.aligned.m16n8k8.row.col.f32.tf32.tf32.f32 "
        "{%0,%1,%2,%3},{%4,%5,%6,%7},{%8,%9},{%0,%1,%2,%3};"
        : "+f"(c[0]), "+f"(c[1]), "+f"(c[2]), "+f"(c[3])
        : "r"(a[0]), "r"(a[1]), "r"(a[2]), "r"(a[3]), "r"(b0), "r"(b1));
}

// ---------------- x pre-conversion (RNA tf32), fused counts zeroing ----------------
__global__ __launch_bounds__(256) void cvt_x_kernel(const float4* __restrict__ in) {
    if (blockIdx.x == 0 && threadIdx.x < NE) g_counts[threadIdx.x] = 0;
    size_t i = (size_t)blockIdx.x * 256 + threadIdx.x;
    if (i < XELEMS / 4) {
        uint4 o = tf32x4(in[i]);
        ((float4*)g_xt)[i] = *(float4*)&o;
    }
}

// ---------------- router (with fused expert counting) ----------------
__global__ __launch_bounds__(256) void router_kernel(const float* __restrict__ x,
                                                     const float* __restrict__ gw) {
    __shared__ float xs[HIDDEN];
    __shared__ float logits[NE];
    int t = blockIdx.x, tid = threadIdx.x;
    const float* xr = x + (size_t)t * HIDDEN;
    for (int i = tid; i < HIDDEN; i += 256) xs[i] = xr[i];
    __syncthreads();
    int w = tid >> 5, lane = tid & 31;
    const float* gr = gw + (size_t)w * HIDDEN;
    float s = 0.f;
    for (int i = lane; i < HIDDEN; i += 32) s += xs[i] * gr[i];
    #pragma unroll
    for (int o = 16; o; o >>= 1) s += __shfl_xor_sync(0xffffffffu, s, o);
    if (lane == 0) logits[w] = s;
    __syncthreads();
    if (tid == 0) {
        float m = logits[0];
        #pragma unroll
        for (int e = 1; e < NE; e++) m = fmaxf(m, logits[e]);
        float p[NE]; float sum = 0.f;
        #pragma unroll
        for (int e = 0; e < NE; e++) { p[e] = __expf(logits[e] - m); sum += p[e]; }
        float inv = 1.f / sum;
        #pragma unroll
        for (int e = 0; e < NE; e++) p[e] *= inv;
        int i1 = 0;
        #pragma unroll
        for (int e = 1; e < NE; e++) if (p[e] > p[i1]) i1 = e;
        int i2 = (i1 == 0) ? 1 : 0;
        #pragma unroll
        for (int e = 0; e < NE; e++) if (e != i1 && e != i2 && p[e] > p[i2]) i2 = e;
        g_topk_idx[2 * t] = i1;     g_topk_w[2 * t] = p[i1];
        g_topk_idx[2 * t + 1] = i2; g_topk_w[2 * t + 1] = p[i2];
        atomicAdd(&g_counts[i1], 1);
        atomicAdd(&g_counts[i2], 1);
    }
}

// build lists; each block also derives the expert offsets locally
__global__ __launch_bounds__(256) void build_lists_kernel() {
    int e = blockIdx.x, tid = threadIdx.x, lane = tid & 31, wid = tid >> 5;
    __shared__ int wsum[8]; __shared__ int sbase; __shared__ int seg_end;
    if (tid == 0) {
        int o = 0, my = 0, tot = 0;
        #pragma unroll
        for (int i = 0; i < NE; i++) {
            int pad = ((g_counts[i] + PADM - 1) / PADM) * PADM;
            if (i == e) my = o;
            o += pad;
            if (i == e) tot = o;
        }
        sbase = my;
        seg_end = tot;
        g_off[e] = my;
        if (e == NE - 1) g_off[NE] = o;
    }
    __syncthreads();
    int seg0 = sbase, segend = seg_end;
    for (int base = 0; base < TOKENS; base += 256) {
        int t = base + tid; int match = 0; float c = 0.f;
        int i0 = g_topk_idx[2 * t], i1 = g_topk_idx[2 * t + 1];
        if (i0 == e) { match = 1; c = g_topk_w[2 * t]; }
        else if (i1 == e) { match = 1; c = g_topk_w[2 * t + 1]; }
        unsigned m = __ballot_sync(0xffffffffu, match);
        if (lane == 0) wsum[wid] = __popc(m);
        __syncthreads();
        int woff = 0, tot = 0;
        #pragma unroll
        for (int i = 0; i < 8; i++) { int v = wsum[i]; if (i < wid) woff += v; tot += v; }
        if (match) { int p = sbase + woff + __popc(m & ((1u << lane) - 1)); g_tok[p] = t; g_coef[p] = c; }
        __syncthreads();
        if (tid == 0) sbase += tot;
        __syncthreads();
    }
    for (int p = seg0 + g_counts[e] + tid; p < segend; p += 256) { g_tok[p] = 0; g_coef[p] = 0.f; }
}

// ---------------- GEMM1: g_h = silu(x@w1^T) * (x@w3^T) ----------------
// CTA tile: M=128, N=128 (each of w1,w3). 3-stage cp.async, all operands async.
// Inner loop uses closed-form swizzle: swz(row*128+col) = row*128 + (col ^ ((row&7)<<4)),
// and all rows a thread touches have row&7 == r -> 2 dynamic offsets per k8.
#define G1_STAGE  49152
#define G1_SMEMSZ (3 * G1_STAGE + 512)

__global__ __launch_bounds__(256, 1) void gemm1_kernel(const float* __restrict__ w1,
                                                       const float* __restrict__ w3) {
    extern __shared__ char sm[];
    const int r0 = blockIdx.y * PADM;
    if (r0 >= g_off[NE]) return;
    int e = 0;
    #pragma unroll
    for (int i = 1; i < NE; i++) if (r0 >= g_off[i]) e = i;
    const int n0 = blockIdx.x * 128;
    const int tid = threadIdx.x, wid = tid >> 5, lane = tid & 31;
    const uint32_t sb = smem_u32(sm);
    int* rtok = (int*)(sm + 3 * G1_STAGE);
    if (tid < 128) rtok[tid] = g_tok[r0 + tid];
    __syncthreads();

    const int lr = tid >> 3, lc = tid & 7;
    const uint32_t as0 = swz(lr * 128 + lc * 16);
    const float* agx[4];
    #pragma unroll
    for (int j = 0; j < 4; j++) agx[j] = g_xt + (size_t)rtok[lr + 32 * j] * HIDDEN + lc * 4;
    const float* b1g = w1 + ((size_t)e * INTER + n0 + lr) * HIDDEN + lc * 4;
    const float* b3g = w3 + ((size_t)e * INTER + n0 + lr) * HIDDEN + lc * 4;

    auto issueStage = [&](int st, int kc) {
        uint32_t base = sb + st * G1_STAGE;
        int k0 = kc * KC;
        #pragma unroll
        for (int j = 0; j < 4; j++) CP_ASYNC16(base + as0 + 4096 * j, agx[j] + k0);
        #pragma unroll
        for (int j = 0; j < 4; j++) CP_ASYNC16(base + 16384 + as0 + 4096 * j, b1g + (size_t)(32 * j) * HIDDEN + k0);
        #pragma unroll
        for (int j = 0; j < 4; j++) CP_ASYNC16(base + 32768 + as0 + 4096 * j, b3g + (size_t)(32 * j) * HIDDEN + k0);
    };

    const int mw = wid & 1, nw = wid >> 1;       // warp = 64M x 32N (per matrix)
    const int r = lane >> 2, q = lane & 3;
    const uint32_t r16 = (uint32_t)r << 4;       // swizzle mask: all rows have row&7 == r
    float accg[4][4][4] = {}, accu[4][4][4] = {};

    issueStage(0, 0); CP_COMMIT();
    issueStage(1, 1); CP_COMMIT();

    const int NCk = HIDDEN / KC;   // 64
    for (int kc = 0; kc < NCk; kc++) {
        const int st = kc % 3;
        CP_WAIT1();
        __syncthreads();
        if (kc + 2 < NCk) issueStage((kc + 2) % 3, kc + 2);
        CP_COMMIT();
        // per-thread row bases (compile-time immediate offsets from these below)
        const char* Ab  = sm + st * G1_STAGE + mw * 8192 + r * 128;   // A row (mw*64 + r)
        const char* B1b = sm + st * G1_STAGE + 16384 + nw * 4096 + r * 128;
        const char* B3b = B1b + 16384;
        #pragma unroll
        for (int k8 = 0; k8 < 4; k8++) {
            const uint32_t c0 = (uint32_t)((k8 * 8 + q) * 4) ^ r16;
            const uint32_t c1 = c0 ^ 16u;
            uint32_t a[4][4];
            #pragma unroll
            for (int i = 0; i < 4; i++) {
                a[i][0] = *(const uint32_t*)(Ab + i * 2048 + c0);
                a[i][1] = *(const uint32_t*)(Ab + i * 2048 + 1024 + c0);
                a[i][2] = *(const uint32_t*)(Ab + i * 2048 + c1);
                a[i][3] = *(const uint32_t*)(Ab + i * 2048 + 1024 + c1);
            }
            #pragma unroll
            for (int j = 0; j < 4; j++) {
                uint32_t b1a = cvt_frag(*(const uint32_t*)(B1b + j * 1024 + c0));
                uint32_t b1c = cvt_frag(*(const uint32_t*)(B1b + j * 1024 + c1));
                uint32_t b3a = cvt_frag(*(const uint32_t*)(B3b + j * 1024 + c0));
                uint32_t b3c = cvt_frag(*(const uint32_t*)(B3b + j * 1024 + c1));
                #pragma unroll
                for (int i = 0; i < 4; i++) {
                    mma8(accg[i][j], a[i], b1a, b1c);
                    mma8(accu[i][j], a[i], b3a, b3c);
                }
            }
        }
    }

    // epilogue: h = rna(silu(g) * u), stored tf32-rounded for gemm2
    #pragma unroll
    for (int i = 0; i < 4; i++) {
        int row0 = r0 + mw * 64 + i * 16 + r;
        #pragma unroll
        for (int j = 0; j < 4; j++) {
            int cg = n0 + nw * 32 + j * 8 + q * 2;
            float g0 = accg[i][j][0], g1 = accg[i][j][1], g2 = accg[i][j][2], g3 = accg[i][j][3];
            float u0 = accu[i][j][0], u1 = accu[i][j][1], u2 = accu[i][j][2], u3 = accu[i][j][3];
            float h0 = rna_tf32((g0 / (1.f + __expf(-g0))) * u0);
            float h1 = rna_tf32((g1 / (1.f + __expf(-g1))) * u1);
            float h2 = rna_tf32((g2 / (1.f + __expf(-g2))) * u2);
            float h3 = rna_tf32((g3 / (1.f + __expf(-g3))) * u3);
            *(float2*)(g_h + (size_t)row0 * INTER + cg)       = make_float2(h0, h1);
            *(float2*)(g_h + (size_t)(row0 + 8) * INTER + cg) = make_float2(h2, h3);
        }
    }
}

// ---------------- GEMM2: out[tok] += coef * (h @ w2^T) ----------------
// CTA tile: M=128, N=256. 3-stage cp.async. Same closed-form swizzle addressing.
#define G2_STAGE  49152
#define G2_SMEMSZ (3 * G2_STAGE + 1024)

__global__ __launch_bounds__(256, 1) void gemm2_kernel(const float* __restrict__ w2,
                                                       float* __restrict__ out) {
    extern __shared__ char sm[];
    const int r0 = blockIdx.y * PADM;
    if (r0 >= g_off[NE]) return;
    int e = 0;
    #pragma unroll
    for (int i = 1; i < NE; i++) if (r0 >= g_off[i]) e = i;
    const int n0 = blockIdx.x * 256;
    const int tid = threadIdx.x, wid = tid >> 5, lane = tid & 31;
    const uint32_t sb = smem_u32(sm);
    int*   rtok  = (int*)(sm + 3 * G2_STAGE);
    float* rcoef = (float*)(sm + 3 * G2_STAGE + 512);
    if (tid < 128) { rtok[tid] = g_tok[r0 + tid]; rcoef[tid] = g_coef[r0 + tid]; }
    __syncthreads();

    const int lr = tid >> 3, lc = tid & 7;
    const uint32_t as0 = swz(lr * 128 + lc * 16);
    const float* ah[4];
    #pragma unroll
    for (int j = 0; j < 4; j++) ah[j] = g_h + (size_t)(r0 + lr + 32 * j) * INTER + lc * 4;
    const float* bg = w2 + ((size_t)e * HIDDEN + n0 + lr) * INTER + lc * 4;

    auto issueStage = [&](int st, int kc) {
        uint32_t base = sb + st * G2_STAGE;
        int k0 = kc * KC;
        #pragma unroll
        for (int j = 0; j < 4; j++) CP_ASYNC16(base + as0 + 4096 * j, ah[j] + k0);
        #pragma unroll
        for (int j = 0; j < 8; j++) CP_ASYNC16(base + 16384 + as0 + 4096 * j, bg + (size_t)(32 * j) * INTER + k0);
    };

    const int mw = wid & 1, nw = wid >> 1;       // warp = 64M x 64N
    const int r = lane >> 2, q = lane & 3;
    const uint32_t r16 = (uint32_t)r << 4;
    float acc[4][8][4] = {};

    issueStage(0, 0); CP_COMMIT();
    issueStage(1, 1); CP_COMMIT();

    const int NCk = INTER / KC;   // 128
    for (int kc = 0; kc < NCk; kc++) {
        const int st = kc % 3;
        CP_WAIT1();
        __syncthreads();
        if (kc + 2 < NCk) issueStage((kc + 2) % 3, kc + 2);
        CP_COMMIT();
        const char* Ab = sm + st * G2_STAGE + mw * 8192 + r * 128;
        const char* Bb = sm + st * G2_STAGE + 16384 + nw * 8192 + r * 128;  // B row (nw*64 + r)
        #pragma unroll
        for (int k8 = 0; k8 < 4; k8++) {
            const uint32_t c0 = (uint32_t)((k8 * 8 + q) * 4) ^ r16;
            const uint32_t c1 = c0 ^ 16u;
            uint32_t a[4][4];
            #pragma unroll
            for (int i = 0; i < 4; i++) {
                a[i][0] = *(const uint32_t*)(Ab + i * 2048 + c0);
                a[i][1] = *(const uint32_t*)(Ab + i * 2048 + 1024 + c0);
                a[i][2] = *(const uint32_t*)(Ab + i * 2048 + c1);
                a[i][3] = *(const uint32_t*)(Ab + i * 2048 + 1024 + c1);
            }
            #pragma unroll
            for (int j = 0; j < 8; j++) {
                uint32_t b0 = cvt_frag(*(const uint32_t*)(Bb + j * 1024 + c0));
                uint32_t b1 = cvt_frag(*(const uint32_t*)(Bb + j * 1024 + c1));
                #pragma unroll
                for (int i = 0; i < 4; i++) mma8(acc[i][j], a[i], b0, b1);
            }
        }
    }

    // epilogue: atomic scatter with routing coefficient
    #pragma unroll
    for (int i = 0; i < 4; i++) {
        int rl = mw * 64 + i * 16 + r;
        float cf0 = rcoef[rl], cf1 = rcoef[rl + 8];
        int   tk0 = rtok[rl],  tk1 = rtok[rl + 8];
        #pragma unroll
        for (int j = 0; j < 8; j++) {
            int cg = n0 + nw * 64 + j * 8 + q * 2;
            if (cf0 != 0.f) {
                float* p = out + (size_t)tk0 * HIDDEN + cg;
                atomicAdd(p,     cf0 * acc[i][j][0]);
                atomicAdd(p + 1, cf0 * acc[i][j][1]);
            }
            if (cf1 != 0.f) {
                float* p = out + (size_t)tk1 * HIDDEN + cg;
                atomicAdd(p,     cf1 * acc[i][j][2]);
                atomicAdd(p + 1, cf1 * acc[i][j][3]);
            }
        }
    }
}

// ---------------- launch ----------------
extern "C" void kernel_launch(void* const* d_in, const int* in_sizes, int n_in,
                              void* d_out, int out_size) {
    const float* x  = (const float*)d_in[0];
    const float* gw = (const float*)d_in[1];
    const float* w1 = (const float*)d_in[2];
    const float* w2 = (const float*)d_in[3];
    const float* w3 = (const float*)d_in[4];
    float* out = (float*)d_out;

    cudaFuncSetAttribute(gemm1_kernel, cudaFuncAttributeMaxDynamicSharedMemorySize, G1_SMEMSZ);
    cudaFuncSetAttribute(gemm2_kernel, cudaFuncAttributeMaxDynamicSharedMemorySize, G2_SMEMSZ);

    // launch order keeps gemm1 at ncu's capture slot (5th launch)
    cudaMemsetAsync(d_out, 0, (size_t)TOKENS * HIDDEN * sizeof(float), 0);   // 1
    cvt_x_kernel<<<(unsigned)(XELEMS / 4 / 256), 256>>>((const float4*)x);   // 2 (zeroes g_counts too)
    router_kernel<<<TOKENS, 256>>>(x, gw);                                   // 3
    build_lists_kernel<<<NE, 256>>>();                                       // 4
    gemm1_kernel<<<dim3(INTER / 128, MT), 256, G1_SMEMSZ>>>(w1, w3);         // 5 <- profiled
    gemm2_kernel<<<dim3(HIDDEN / 256, MT), 256, G2_SMEMSZ>>>(w2, out);       // 6
}

// round 15
// speedup vs baseline: 1.5000x; 1.0014x over previous
#include <cuda_runtime.h>
#include <cstdint>
#include <math.h>

#define NE      8
#define HIDDEN  2048
#define INTER   4096
#define TOKENS  8192
#define SLOTS   (TOKENS * 2)
#define PADM    128
#define SLOTS_PAD (SLOTS + NE * PADM)   // 17408
#define MT      (SLOTS_PAD / PADM)      // 136
#define KC      32                      // K elems per pipeline chunk
#define XELEMS  ((size_t)TOKENS * HIDDEN)

// ---------------- scratch (device globals: allocation-free, ~352 MB total) ----------------
__device__ int   g_topk_idx[SLOTS];
__device__ float g_topk_w[SLOTS];
__device__ int   g_counts[NE];
__device__ int   g_off[NE + 1];
__device__ int   g_tok[SLOTS_PAD];
__device__ float g_coef[SLOTS_PAD];
__device__ float g_h[(size_t)SLOTS_PAD * INTER];   // ~285 MB
__device__ float g_xt[XELEMS];                     // tf32-rounded x (~67 MB)

// ---------------- helpers ----------------
__device__ __forceinline__ uint32_t smem_u32(const void* p) {
    uint32_t a;
    asm("{ .reg .u64 t; cvta.to.shared.u64 t, %1; cvt.u32.u64 %0, t; }" : "=r"(a) : "l"(p));
    return a;
}
__device__ __forceinline__ uint32_t swz(uint32_t off) { return off ^ ((off >> 3) & 0x70); }

__device__ __forceinline__ float rna_tf32(float f) {
    uint32_t r;
    asm("cvt.rna.tf32.f32 %0, %1;" : "=r"(r) : "f"(f));
    return __uint_as_float(r);
}
__device__ __forceinline__ uint32_t cvt_frag(uint32_t raw) {
    uint32_t r;
    asm("cvt.rna.tf32.f32 %0, %1;" : "=r"(r) : "f"(__uint_as_float(raw)));
    return r;
}
__device__ __forceinline__ uint4 tf32x4(float4 v) {
    uint4 r;
    asm("cvt.rna.tf32.f32 %0, %1;" : "=r"(r.x) : "f"(v.x));
    asm("cvt.rna.tf32.f32 %0, %1;" : "=r"(r.y) : "f"(v.y));
    asm("cvt.rna.tf32.f32 %0, %1;" : "=r"(r.z) : "f"(v.z));
    asm("cvt.rna.tf32.f32 %0, %1;" : "=r"(r.w) : "f"(v.w));
    return r;
}

#define CP_ASYNC16(s, g) asm volatile("cp.async.cg.shared.global [%0], [%1], 16;" :: "r"(s), "l"(g))
#define CP_COMMIT()      asm volatile("cp.async.commit_group;" ::: "memory")
#define CP_WAIT2()       asm volatile("cp.async.wait_group 2;" ::: "memory")

// m16n8k8 tf32 mma: D/C fp32, A row-major, B col-major
__device__ __forceinline__ void mma8(float* c, const uint32_t* a, uint32_t b0, uint32_t b1) {
    asm volatile(
        "mma.sync.aligned.m16n8k8.row.col.f32.tf32.tf32.f32 "
        "{%0,%1,%2,%3},{%4,%5,%6,%7},{%8,%9},{%0,%1,%2,%3};"
        : "+f"(c[0]), "+f"(c[1]), "+f"(c[2]), "+f"(c[3])
        : "r"(a[0]), "r"(a[1]), "r"(a[2]), "r"(a[3]), "r"(b0), "r"(b1));
}

// ---------------- x pre-conversion (RNA tf32), fused counts zeroing ----------------
__global__ __launch_bounds__(256) void cvt_x_kernel(const float4* __restrict__ in) {
    if (blockIdx.x == 0 && threadIdx.x < NE) g_counts[threadIdx.x] = 0;
    size_t i = (size_t)blockIdx.x * 256 + threadIdx.x;
    if (i < XELEMS / 4) {
        uint4 o = tf32x4(in[i]);
        ((float4*)g_xt)[i] = *(float4*)&o;
    }
}

// ---------------- router (with fused expert counting) ----------------
__global__ __launch_bounds__(256) void router_kernel(const float* __restrict__ x,
                                                     const float* __restrict__ gw) {
    __shared__ float xs[HIDDEN];
    __shared__ float logits[NE];
    int t = blockIdx.x, tid = threadIdx.x;
    const float* xr = x + (size_t)t * HIDDEN;
    for (int i = tid; i < HIDDEN; i += 256) xs[i] = xr[i];
    __syncthreads();
    int w = tid >> 5, lane = tid & 31;
    const float* gr = gw + (size_t)w * HIDDEN;
    float s = 0.f;
    for (int i = lane; i < HIDDEN; i += 32) s += xs[i] * gr[i];
    #pragma unroll
    for (int o = 16; o; o >>= 1) s += __shfl_xor_sync(0xffffffffu, s, o);
    if (lane == 0) logits[w] = s;
    __syncthreads();
    if (tid == 0) {
        float m = logits[0];
        #pragma unroll
        for (int e = 1; e < NE; e++) m = fmaxf(m, logits[e]);
        float p[NE]; float sum = 0.f;
        #pragma unroll
        for (int e = 0; e < NE; e++) { p[e] = __expf(logits[e] - m); sum += p[e]; }
        float inv = 1.f / sum;
        #pragma unroll
        for (int e = 0; e < NE; e++) p[e] *= inv;
        int i1 = 0;
        #pragma unroll
        for (int e = 1; e < NE; e++) if (p[e] > p[i1]) i1 = e;
        int i2 = (i1 == 0) ? 1 : 0;
        #pragma unroll
        for (int e = 0; e < NE; e++) if (e != i1 && e != i2 && p[e] > p[i2]) i2 = e;
        g_topk_idx[2 * t] = i1;     g_topk_w[2 * t] = p[i1];
        g_topk_idx[2 * t + 1] = i2; g_topk_w[2 * t + 1] = p[i2];
        atomicAdd(&g_counts[i1], 1);
        atomicAdd(&g_counts[i2], 1);
    }
}

// build lists; each block also derives the expert offsets locally
__global__ __launch_bounds__(256) void build_lists_kernel() {
    int e = blockIdx.x, tid = threadIdx.x, lane = tid & 31, wid = tid >> 5;
    __shared__ int wsum[8]; __shared__ int sbase; __shared__ int seg_end;
    if (tid == 0) {
        int o = 0, my = 0, tot = 0;
        #pragma unroll
        for (int i = 0; i < NE; i++) {
            int pad = ((g_counts[i] + PADM - 1) / PADM) * PADM;
            if (i == e) my = o;
            o += pad;
            if (i == e) tot = o;
        }
        sbase = my;
        seg_end = tot;
        g_off[e] = my;
        if (e == NE - 1) g_off[NE] = o;
    }
    __syncthreads();
    int seg0 = sbase, segend = seg_end;
    for (int base = 0; base < TOKENS; base += 256) {
        int t = base + tid; int match = 0; float c = 0.f;
        int i0 = g_topk_idx[2 * t], i1 = g_topk_idx[2 * t + 1];
        if (i0 == e) { match = 1; c = g_topk_w[2 * t]; }
        else if (i1 == e) { match = 1; c = g_topk_w[2 * t + 1]; }
        unsigned m = __ballot_sync(0xffffffffu, match);
        if (lane == 0) wsum[wid] = __popc(m);
        __syncthreads();
        int woff = 0, tot = 0;
        #pragma unroll
        for (int i = 0; i < 8; i++) { int v = wsum[i]; if (i < wid) woff += v; tot += v; }
        if (match) { int p = sbase + woff + __popc(m & ((1u << lane) - 1)); g_tok[p] = t; g_coef[p] = c; }
        __syncthreads();
        if (tid == 0) sbase += tot;
        __syncthreads();
    }
    for (int p = seg0 + g_counts[e] + tid; p < segend; p += 256) { g_tok[p] = 0; g_coef[p] = 0.f; }
}

// ---------------- GEMM1: g_h = silu(x@w1^T) * (x@w3^T) ----------------
// CTA tile: M=128, N=128 (each of w1,w3). 4-stage cp.async; closed-form swizzle;
// per-k8 all fragment LDS hoisted ahead of cvt+mma (MLP 32).
#define G1_STAGE  49152
#define G1_SMEMSZ (4 * G1_STAGE + 512)

__global__ __launch_bounds__(256, 1) void gemm1_kernel(const float* __restrict__ w1,
                                                       const float* __restrict__ w3) {
    extern __shared__ char sm[];
    const int r0 = blockIdx.y * PADM;
    if (r0 >= g_off[NE]) return;
    int e = 0;
    #pragma unroll
    for (int i = 1; i < NE; i++) if (r0 >= g_off[i]) e = i;
    const int n0 = blockIdx.x * 128;
    const int tid = threadIdx.x, wid = tid >> 5, lane = tid & 31;
    const uint32_t sb = smem_u32(sm);
    int* rtok = (int*)(sm + 4 * G1_STAGE);
    if (tid < 128) rtok[tid] = g_tok[r0 + tid];
    __syncthreads();

    const int lr = tid >> 3, lc = tid & 7;
    const uint32_t as0 = swz(lr * 128 + lc * 16);
    const float* agx[4];
    #pragma unroll
    for (int j = 0; j < 4; j++) agx[j] = g_xt + (size_t)rtok[lr + 32 * j] * HIDDEN + lc * 4;
    const float* b1g = w1 + ((size_t)e * INTER + n0 + lr) * HIDDEN + lc * 4;
    const float* b3g = w3 + ((size_t)e * INTER + n0 + lr) * HIDDEN + lc * 4;

    auto issueStage = [&](int st, int kc) {
        uint32_t base = sb + st * G1_STAGE;
        int k0 = kc * KC;
        #pragma unroll
        for (int j = 0; j < 4; j++) CP_ASYNC16(base + as0 + 4096 * j, agx[j] + k0);
        #pragma unroll
        for (int j = 0; j < 4; j++) CP_ASYNC16(base + 16384 + as0 + 4096 * j, b1g + (size_t)(32 * j) * HIDDEN + k0);
        #pragma unroll
        for (int j = 0; j < 4; j++) CP_ASYNC16(base + 32768 + as0 + 4096 * j, b3g + (size_t)(32 * j) * HIDDEN + k0);
    };

    const int mw = wid & 1, nw = wid >> 1;       // warp = 64M x 32N (per matrix)
    const int r = lane >> 2, q = lane & 3;
    const uint32_t r16 = (uint32_t)r << 4;
    float accg[4][4][4] = {}, accu[4][4][4] = {};

    issueStage(0, 0); CP_COMMIT();
    issueStage(1, 1); CP_COMMIT();
    issueStage(2, 2); CP_COMMIT();

    const int NCk = HIDDEN / KC;   // 64
    for (int kc = 0; kc < NCk; kc++) {
        const int st = kc & 3;
        CP_WAIT2();                // stage kc landed (committed 3 groups ago)
        __syncthreads();
        if (kc + 3 < NCk) issueStage((kc + 3) & 3, kc + 3);
        CP_COMMIT();
        const char* Ab  = sm + st * G1_STAGE + mw * 8192 + r * 128;
        const char* B1b = sm + st * G1_STAGE + 16384 + nw * 4096 + r * 128;
        const char* B3b = B1b + 16384;
        #pragma unroll
        for (int k8 = 0; k8 < 4; k8++) {
            const uint32_t c0 = (uint32_t)((k8 * 8 + q) * 4) ^ r16;
            const uint32_t c1 = c0 ^ 16u;
            // --- all fragment loads issued first (MLP 32) ---
            uint32_t a[4][4];
            #pragma unroll
            for (int i = 0; i < 4; i++) {
                a[i][0] = *(const uint32_t*)(Ab + i * 2048 + c0);
                a[i][1] = *(const uint32_t*)(Ab + i * 2048 + 1024 + c0);
                a[i][2] = *(const uint32_t*)(Ab + i * 2048 + c1);
                a[i][3] = *(const uint32_t*)(Ab + i * 2048 + 1024 + c1);
            }
            uint32_t b1r[8], b3r[8];
            #pragma unroll
            for (int j = 0; j < 4; j++) {
                b1r[2 * j]     = *(const uint32_t*)(B1b + j * 1024 + c0);
                b1r[2 * j + 1] = *(const uint32_t*)(B1b + j * 1024 + c1);
                b3r[2 * j]     = *(const uint32_t*)(B3b + j * 1024 + c0);
                b3r[2 * j + 1] = *(const uint32_t*)(B3b + j * 1024 + c1);
            }
            // --- cvt + mma ---
            #pragma unroll
            for (int j = 0; j < 4; j++) {
                uint32_t b1a = cvt_frag(b1r[2 * j]);
                uint32_t b1c = cvt_frag(b1r[2 * j + 1]);
                uint32_t b3a = cvt_frag(b3r[2 * j]);
                uint32_t b3c = cvt_frag(b3r[2 * j + 1]);
                #pragma unroll
                for (int i = 0; i < 4; i++) {
                    mma8(accg[i][j], a[i], b1a, b1c);
                    mma8(accu[i][j], a[i], b3a, b3c);
                }
            }
        }
    }

    // epilogue: h = rna(silu(g) * u), stored tf32-rounded for gemm2
    #pragma unroll
    for (int i = 0; i < 4; i++) {
        int row0 = r0 + mw * 64 + i * 16 + r;
        #pragma unroll
        for (int j = 0; j < 4; j++) {
            int cg = n0 + nw * 32 + j * 8 + q * 2;
            float g0 = accg[i][j][0], g1 = accg[i][j][1], g2 = accg[i][j][2], g3 = accg[i][j][3];
            float u0 = accu[i][j][0], u1 = accu[i][j][1], u2 = accu[i][j][2], u3 = accu[i][j][3];
            float h0 = rna_tf32((g0 / (1.f + __expf(-g0))) * u0);
            float h1 = rna_tf32((g1 / (1.f + __expf(-g1))) * u1);
            float h2 = rna_tf32((g2 / (1.f + __expf(-g2))) * u2);
            float h3 = rna_tf32((g3 / (1.f + __expf(-g3))) * u3);
            *(float2*)(g_h + (size_t)row0 * INTER + cg)       = make_float2(h0, h1);
            *(float2*)(g_h + (size_t)(row0 + 8) * INTER + cg) = make_float2(h2, h3);
        }
    }
}

// ---------------- GEMM2: out[tok] += coef * (h @ w2^T) ----------------
// CTA tile: M=128, N=256. 4-stage cp.async; hoisted fragment loads.
#define G2_STAGE  49152
#define G2_SMEMSZ (4 * G2_STAGE + 1024)

__global__ __launch_bounds__(256, 1) void gemm2_kernel(const float* __restrict__ w2,
                                                       float* __restrict__ out) {
    extern __shared__ char sm[];
    const int r0 = blockIdx.y * PADM;
    if (r0 >= g_off[NE]) return;
    int e = 0;
    #pragma unroll
    for (int i = 1; i < NE; i++) if (r0 >= g_off[i]) e = i;
    const int n0 = blockIdx.x * 256;
    const int tid = threadIdx.x, wid = tid >> 5, lane = tid & 31;
    const uint32_t sb = smem_u32(sm);
    int*   rtok  = (int*)(sm + 4 * G2_STAGE);
    float* rcoef = (float*)(sm + 4 * G2_STAGE + 512);
    if (tid < 128) { rtok[tid] = g_tok[r0 + tid]; rcoef[tid] = g_coef[r0 + tid]; }
    __syncthreads();

    const int lr = tid >> 3, lc = tid & 7;
    const uint32_t as0 = swz(lr * 128 + lc * 16);
    const float* ah[4];
    #pragma unroll
    for (int j = 0; j < 4; j++) ah[j] = g_h + (size_t)(r0 + lr + 32 * j) * INTER + lc * 4;
    const float* bg = w2 + ((size_t)e * HIDDEN + n0 + lr) * INTER + lc * 4;

    auto issueStage = [&](int st, int kc) {
        uint32_t base = sb + st * G2_STAGE;
        int k0 = kc * KC;
        #pragma unroll
        for (int j = 0; j < 4; j++) CP_ASYNC16(base + as0 + 4096 * j, ah[j] + k0);
        #pragma unroll
        for (int j = 0; j < 8; j++) CP_ASYNC16(base + 16384 + as0 + 4096 * j, bg + (size_t)(32 * j) * INTER + k0);
    };

    const int mw = wid & 1, nw = wid >> 1;       // warp = 64M x 64N
    const int r = lane >> 2, q = lane & 3;
    const uint32_t r16 = (uint32_t)r << 4;
    float acc[4][8][4] = {};

    issueStage(0, 0); CP_COMMIT();
    issueStage(1, 1); CP_COMMIT();
    issueStage(2, 2); CP_COMMIT();

    const int NCk = INTER / KC;   // 128
    for (int kc = 0; kc < NCk; kc++) {
        const int st = kc & 3;
        CP_WAIT2();
        __syncthreads();
        if (kc + 3 < NCk) issueStage((kc + 3) & 3, kc + 3);
        CP_COMMIT();
        const char* Ab = sm + st * G2_STAGE + mw * 8192 + r * 128;
        const char* Bb = sm + st * G2_STAGE + 16384 + nw * 8192 + r * 128;
        #pragma unroll
        for (int k8 = 0; k8 < 4; k8++) {
            const uint32_t c0 = (uint32_t)((k8 * 8 + q) * 4) ^ r16;
            const uint32_t c1 = c0 ^ 16u;
            uint32_t a[4][4];
            #pragma unroll
            for (int i = 0; i < 4; i++) {
                a[i][0] = *(const uint32_t*)(Ab + i * 2048 + c0);
                a[i][1] = *(const uint32_t*)(Ab + i * 2048 + 1024 + c0);
                a[i][2] = *(const uint32_t*)(Ab + i * 2048 + c1);
                a[i][3] = *(const uint32_t*)(Ab + i * 2048 + 1024 + c1);
            }
            uint32_t br[16];
            #pragma unroll
            for (int j = 0; j < 8; j++) {
                br[2 * j]     = *(const uint32_t*)(Bb + j * 1024 + c0);
                br[2 * j + 1] = *(const uint32_t*)(Bb + j * 1024 + c1);
            }
            #pragma unroll
            for (int j = 0; j < 8; j++) {
                uint32_t b0 = cvt_frag(br[2 * j]);
                uint32_t b1 = cvt_frag(br[2 * j + 1]);
                #pragma unroll
                for (int i = 0; i < 4; i++) mma8(acc[i][j], a[i], b0, b1);
            }
        }
    }

    // epilogue: atomic scatter with routing coefficient
    #pragma unroll
    for (int i = 0; i < 4; i++) {
        int rl = mw * 64 + i * 16 + r;
        float cf0 = rcoef[rl], cf1 = rcoef[rl + 8];
        int   tk0 = rtok[rl],  tk1 = rtok[rl + 8];
        #pragma unroll
        for (int j = 0; j < 8; j++) {
            int cg = n0 + nw * 64 + j * 8 + q * 2;
            if (cf0 != 0.f) {
                float* p = out + (size_t)tk0 * HIDDEN + cg;
                atomicAdd(p,     cf0 * acc[i][j][0]);
                atomicAdd(p + 1, cf0 * acc[i][j][1]);
            }
            if (cf1 != 0.f) {
                float* p = out + (size_t)tk1 * HIDDEN + cg;
                atomicAdd(p,     cf1 * acc[i][j][2]);
                atomicAdd(p + 1, cf1 * acc[i][j][3]);
            }
        }
    }
}

// ---------------- launch ----------------
extern "C" void kernel_launch(void* const* d_in, const int* in_sizes, int n_in,
                              void* d_out, int out_size) {
    const float* x  = (const float*)d_in[0];
    const float* gw = (const float*)d_in[1];
    const float* w1 = (const float*)d_in[2];
    const float* w2 = (const float*)d_in[3];
    const float* w3 = (const float*)d_in[4];
    float* out = (float*)d_out;

    cudaFuncSetAttribute(gemm1_kernel, cudaFuncAttributeMaxDynamicSharedMemorySize, G1_SMEMSZ);
    cudaFuncSetAttribute(gemm2_kernel, cudaFuncAttributeMaxDynamicSharedMemorySize, G2_SMEMSZ);

    // launch order keeps gemm1 at ncu's capture slot (5th launch)
    cudaMemsetAsync(d_out, 0, (size_t)TOKENS * HIDDEN * sizeof(float), 0);   // 1
    cvt_x_kernel<<<(unsigned)(XELEMS / 4 / 256), 256>>>((const float4*)x);   // 2 (zeroes g_counts too)
    router_kernel<<<TOKENS, 256>>>(x, gw);                                   // 3
    build_lists_kernel<<<NE, 256>>>();                                       // 4
    gemm1_kernel<<<dim3(INTER / 128, MT), 256, G1_SMEMSZ>>>(w1, w3);         // 5 <- profiled
    gemm2_kernel<<<dim3(HIDDEN / 256, MT), 256, G2_SMEMSZ>>>(w2, out);       // 6
}

// round 16
// speedup vs baseline: 1.5965x; 1.0643x over previous
#include <cuda_runtime.h>
#include <cstdint>
#include <math.h>

#define NE      8
#define HIDDEN  2048
#define INTER   4096
#define TOKENS  8192
#define SLOTS   (TOKENS * 2)
#define PADM    128
#define SLOTS_PAD (SLOTS + NE * PADM)   // 17408
#define MT      (SLOTS_PAD / PADM)      // 136
#define KC      32                      // K elems per pipeline chunk
#define XELEMS  ((size_t)TOKENS * HIDDEN)

// ---------------- scratch (device globals: allocation-free, ~352 MB total) ----------------
__device__ int   g_topk_idx[SLOTS];
__device__ float g_topk_w[SLOTS];
__device__ int   g_counts[NE];
__device__ int   g_off[NE + 1];
__device__ int   g_tok[SLOTS_PAD];
__device__ float g_coef[SLOTS_PAD];
__device__ float g_h[(size_t)SLOTS_PAD * INTER];   // ~285 MB
__device__ float g_xt[XELEMS];                     // tf32-rounded x (~67 MB)

// ---------------- helpers ----------------
__device__ __forceinline__ uint32_t smem_u32(const void* p) {
    uint32_t a;
    asm("{ .reg .u64 t; cvta.to.shared.u64 t, %1; cvt.u32.u64 %0, t; }" : "=r"(a) : "l"(p));
    return a;
}
__device__ __forceinline__ uint32_t swz(uint32_t off) { return off ^ ((off >> 3) & 0x70); }

__device__ __forceinline__ float rna_tf32(float f) {
    uint32_t r;
    asm("cvt.rna.tf32.f32 %0, %1;" : "=r"(r) : "f"(f));
    return __uint_as_float(r);
}
__device__ __forceinline__ uint32_t cvt_frag(uint32_t raw) {
    uint32_t r;
    asm("cvt.rna.tf32.f32 %0, %1;" : "=r"(r) : "f"(__uint_as_float(raw)));
    return r;
}
__device__ __forceinline__ uint4 tf32x4(float4 v) {
    uint4 r;
    asm("cvt.rna.tf32.f32 %0, %1;" : "=r"(r.x) : "f"(v.x));
    asm("cvt.rna.tf32.f32 %0, %1;" : "=r"(r.y) : "f"(v.y));
    asm("cvt.rna.tf32.f32 %0, %1;" : "=r"(r.z) : "f"(v.z));
    asm("cvt.rna.tf32.f32 %0, %1;" : "=r"(r.w) : "f"(v.w));
    return r;
}

#define CP_ASYNC16(s, g) asm volatile("cp.async.cg.shared.global [%0], [%1], 16;" :: "r"(s), "l"(g))
#define CP_COMMIT()      asm volatile("cp.async.commit_group;" ::: "memory")
#define CP_WAIT2()       asm volatile("cp.async.wait_group 2;" ::: "memory")

// m16n8k8 tf32 mma: D/C fp32, A row-major, B col-major
__device__ __forceinline__ void mma8(float* c, const uint32_t* a, uint32_t b0, uint32_t b1) {
    asm volatile(
        "mma.sync.aligned.m16n8k8.row.col.f32.tf32.tf32.f32 "
        "{%0,%1,%2,%3},{%4,%5,%6,%7},{%8,%9},{%0,%1,%2,%3};"
        : "+f"(c[0]), "+f"(c[1]), "+f"(c[2]), "+f"(c[3])
        : "r"(a[0]), "r"(a[1]), "r"(a[2]), "r"(a[3]), "r"(b0), "r"(b1));
}

// ---------------- x pre-conversion (RNA tf32), fused counts zeroing ----------------
__global__ __launch_bounds__(256) void cvt_x_kernel(const float4* __restrict__ in) {
    if (blockIdx.x == 0 && threadIdx.x < NE) g_counts[threadIdx.x] = 0;
    size_t i = (size_t)blockIdx.x * 256 + threadIdx.x;
    if (i < XELEMS / 4) {
        uint4 o = tf32x4(in[i]);
        ((float4*)g_xt)[i] = *(float4*)&o;
    }
}

// ---------------- router (with fused expert counting) ----------------
__global__ __launch_bounds__(256) void router_kernel(const float* __restrict__ x,
                                                     const float* __restrict__ gw) {
    __shared__ float xs[HIDDEN];
    __shared__ float logits[NE];
    int t = blockIdx.x, tid = threadIdx.x;
    const float* xr = x + (size_t)t * HIDDEN;
    for (int i = tid; i < HIDDEN; i += 256) xs[i] = xr[i];
    __syncthreads();
    int w = tid >> 5, lane = tid & 31;
    const float* gr = gw + (size_t)w * HIDDEN;
    float s = 0.f;
    for (int i = lane; i < HIDDEN; i += 32) s += xs[i] * gr[i];
    #pragma unroll
    for (int o = 16; o; o >>= 1) s += __shfl_xor_sync(0xffffffffu, s, o);
    if (lane == 0) logits[w] = s;
    __syncthreads();
    if (tid == 0) {
        float m = logits[0];
        #pragma unroll
        for (int e = 1; e < NE; e++) m = fmaxf(m, logits[e]);
        float p[NE]; float sum = 0.f;
        #pragma unroll
        for (int e = 0; e < NE; e++) { p[e] = __expf(logits[e] - m); sum += p[e]; }
        float inv = 1.f / sum;
        #pragma unroll
        for (int e = 0; e < NE; e++) p[e] *= inv;
        int i1 = 0;
        #pragma unroll
        for (int e = 1; e < NE; e++) if (p[e] > p[i1]) i1 = e;
        int i2 = (i1 == 0) ? 1 : 0;
        #pragma unroll
        for (int e = 0; e < NE; e++) if (e != i1 && e != i2 && p[e] > p[i2]) i2 = e;
        g_topk_idx[2 * t] = i1;     g_topk_w[2 * t] = p[i1];
        g_topk_idx[2 * t + 1] = i2; g_topk_w[2 * t + 1] = p[i2];
        atomicAdd(&g_counts[i1], 1);
        atomicAdd(&g_counts[i2], 1);
    }
}

// build lists; each block also derives the expert offsets locally
__global__ __launch_bounds__(256) void build_lists_kernel() {
    int e = blockIdx.x, tid = threadIdx.x, lane = tid & 31, wid = tid >> 5;
    __shared__ int wsum[8]; __shared__ int sbase; __shared__ int seg_end;
    if (tid == 0) {
        int o = 0, my = 0, tot = 0;
        #pragma unroll
        for (int i = 0; i < NE; i++) {
            int pad = ((g_counts[i] + PADM - 1) / PADM) * PADM;
            if (i == e) my = o;
            o += pad;
            if (i == e) tot = o;
        }
        sbase = my;
        seg_end = tot;
        g_off[e] = my;
        if (e == NE - 1) g_off[NE] = o;
    }
    __syncthreads();
    int seg0 = sbase, segend = seg_end;
    for (int base = 0; base < TOKENS; base += 256) {
        int t = base + tid; int match = 0; float c = 0.f;
        int i0 = g_topk_idx[2 * t], i1 = g_topk_idx[2 * t + 1];
        if (i0 == e) { match = 1; c = g_topk_w[2 * t]; }
        else if (i1 == e) { match = 1; c = g_topk_w[2 * t + 1]; }
        unsigned m = __ballot_sync(0xffffffffu, match);
        if (lane == 0) wsum[wid] = __popc(m);
        __syncthreads();
        int woff = 0, tot = 0;
        #pragma unroll
        for (int i = 0; i < 8; i++) { int v = wsum[i]; if (i < wid) woff += v; tot += v; }
        if (match) { int p = sbase + woff + __popc(m & ((1u << lane) - 1)); g_tok[p] = t; g_coef[p] = c; }
        __syncthreads();
        if (tid == 0) sbase += tot;
        __syncthreads();
    }
    for (int p = seg0 + g_counts[e] + tid; p < segend; p += 256) { g_tok[p] = 0; g_coef[p] = 0.f; }
}

// ---------------- GEMM1: g_h = silu(x@w1^T) * (x@w3^T) ----------------
// CTA tile: M=128, N=128 (each of w1,w3). 4-stage cp.async; closed-form swizzle.
// Prefetch cp.asyncs SPREAD across k8 iterations (3 per k8) to keep the LSU
// burst off the post-barrier critical path; one commit per chunk.
#define G1_STAGE  49152
#define G1_SMEMSZ (4 * G1_STAGE + 512)

__global__ __launch_bounds__(256, 1) void gemm1_kernel(const float* __restrict__ w1,
                                                       const float* __restrict__ w3) {
    extern __shared__ char sm[];
    const int r0 = blockIdx.y * PADM;
    if (r0 >= g_off[NE]) return;
    int e = 0;
    #pragma unroll
    for (int i = 1; i < NE; i++) if (r0 >= g_off[i]) e = i;
    const int n0 = blockIdx.x * 128;
    const int tid = threadIdx.x, wid = tid >> 5, lane = tid & 31;
    const uint32_t sb = smem_u32(sm);
    int* rtok = (int*)(sm + 4 * G1_STAGE);
    if (tid < 128) rtok[tid] = g_tok[r0 + tid];
    __syncthreads();

    const int lr = tid >> 3, lc = tid & 7;
    const uint32_t as0 = swz(lr * 128 + lc * 16);
    const float* agx[4];
    #pragma unroll
    for (int j = 0; j < 4; j++) agx[j] = g_xt + (size_t)rtok[lr + 32 * j] * HIDDEN + lc * 4;
    const float* b1g = w1 + ((size_t)e * INTER + n0 + lr) * HIDDEN + lc * 4;
    const float* b3g = w3 + ((size_t)e * INTER + n0 + lr) * HIDDEN + lc * 4;

    auto issueStage = [&](int st, int kc) {
        uint32_t base = sb + st * G1_STAGE;
        int k0 = kc * KC;
        #pragma unroll
        for (int j = 0; j < 4; j++) CP_ASYNC16(base + as0 + 4096 * j, agx[j] + k0);
        #pragma unroll
        for (int j = 0; j < 4; j++) CP_ASYNC16(base + 16384 + as0 + 4096 * j, b1g + (size_t)(32 * j) * HIDDEN + k0);
        #pragma unroll
        for (int j = 0; j < 4; j++) CP_ASYNC16(base + 32768 + as0 + 4096 * j, b3g + (size_t)(32 * j) * HIDDEN + k0);
    };

    const int mw = wid & 1, nw = wid >> 1;       // warp = 64M x 32N (per matrix)
    const int r = lane >> 2, q = lane & 3;
    const uint32_t r16 = (uint32_t)r << 4;
    float accg[4][4][4] = {}, accu[4][4][4] = {};

    issueStage(0, 0); CP_COMMIT();
    issueStage(1, 1); CP_COMMIT();
    issueStage(2, 2); CP_COMMIT();

    const int NCk = HIDDEN / KC;   // 64
    for (int kc = 0; kc < NCk; kc++) {
        const int st = kc & 3;
        CP_WAIT2();                // stage kc landed (committed 3 groups ago)
        __syncthreads();
        const bool pf = (kc + 3 < NCk);
        const uint32_t pbase = sb + ((kc + 3) & 3) * G1_STAGE;
        const int pk0 = (kc + 3) * KC;
        const char* Ab  = sm + st * G1_STAGE + mw * 8192 + r * 128;
        const char* B1b = sm + st * G1_STAGE + 16384 + nw * 4096 + r * 128;
        const char* B3b = B1b + 16384;
        #pragma unroll
        for (int k8 = 0; k8 < 4; k8++) {
            const uint32_t c0 = (uint32_t)((k8 * 8 + q) * 4) ^ r16;
            const uint32_t c1 = c0 ^ 16u;
            uint32_t a[4][4];
            #pragma unroll
            for (int i = 0; i < 4; i++) {
                a[i][0] = *(const uint32_t*)(Ab + i * 2048 + c0);
                a[i][1] = *(const uint32_t*)(Ab + i * 2048 + 1024 + c0);
                a[i][2] = *(const uint32_t*)(Ab + i * 2048 + c1);
                a[i][3] = *(const uint32_t*)(Ab + i * 2048 + 1024 + c1);
            }
            uint32_t b1r[8], b3r[8];
            #pragma unroll
            for (int j = 0; j < 4; j++) {
                b1r[2 * j]     = *(const uint32_t*)(B1b + j * 1024 + c0);
                b1r[2 * j + 1] = *(const uint32_t*)(B1b + j * 1024 + c1);
                b3r[2 * j]     = *(const uint32_t*)(B3b + j * 1024 + c0);
                b3r[2 * j + 1] = *(const uint32_t*)(B3b + j * 1024 + c1);
            }
            // spread prefetch: 3 cp.asyncs of stage kc+3 per k8 (A/B1/B3 slice k8)
            if (pf) {
                CP_ASYNC16(pbase + as0 + 4096 * k8, agx[k8] + pk0);
                CP_ASYNC16(pbase + 16384 + as0 + 4096 * k8, b1g + (size_t)(32 * k8) * HIDDEN + pk0);
                CP_ASYNC16(pbase + 32768 + as0 + 4096 * k8, b3g + (size_t)(32 * k8) * HIDDEN + pk0);
            }
            #pragma unroll
            for (int j = 0; j < 4; j++) {
                uint32_t b1a = cvt_frag(b1r[2 * j]);
                uint32_t b1c = cvt_frag(b1r[2 * j + 1]);
                uint32_t b3a = cvt_frag(b3r[2 * j]);
                uint32_t b3c = cvt_frag(b3r[2 * j + 1]);
                #pragma unroll
                for (int i = 0; i < 4; i++) {
                    mma8(accg[i][j], a[i], b1a, b1c);
                    mma8(accu[i][j], a[i], b3a, b3c);
                }
            }
        }
        CP_COMMIT();               // one group per chunk (empty at tail)
    }

    // epilogue: h = rna(silu(g) * u), stored tf32-rounded for gemm2
    #pragma unroll
    for (int i = 0; i < 4; i++) {
        int row0 = r0 + mw * 64 + i * 16 + r;
        #pragma unroll
        for (int j = 0; j < 4; j++) {
            int cg = n0 + nw * 32 + j * 8 + q * 2;
            float g0 = accg[i][j][0], g1 = accg[i][j][1], g2 = accg[i][j][2], g3 = accg[i][j][3];
            float u0 = accu[i][j][0], u1 = accu[i][j][1], u2 = accu[i][j][2], u3 = accu[i][j][3];
            float h0 = rna_tf32((g0 / (1.f + __expf(-g0))) * u0);
            float h1 = rna_tf32((g1 / (1.f + __expf(-g1))) * u1);
            float h2 = rna_tf32((g2 / (1.f + __expf(-g2))) * u2);
            float h3 = rna_tf32((g3 / (1.f + __expf(-g3))) * u3);
            *(float2*)(g_h + (size_t)row0 * INTER + cg)       = make_float2(h0, h1);
            *(float2*)(g_h + (size_t)(row0 + 8) * INTER + cg) = make_float2(h2, h3);
        }
    }
}

// ---------------- GEMM2: out[tok] += coef * (h @ w2^T) ----------------
// CTA tile: M=128, N=256. 4-stage cp.async; spread prefetch (3 per k8).
#define G2_STAGE  49152
#define G2_SMEMSZ (4 * G2_STAGE + 1024)

__global__ __launch_bounds__(256, 1) void gemm2_kernel(const float* __restrict__ w2,
                                                       float* __restrict__ out) {
    extern __shared__ char sm[];
    const int r0 = blockIdx.y * PADM;
    if (r0 >= g_off[NE]) return;
    int e = 0;
    #pragma unroll
    for (int i = 1; i < NE; i++) if (r0 >= g_off[i]) e = i;
    const int n0 = blockIdx.x * 256;
    const int tid = threadIdx.x, wid = tid >> 5, lane = tid & 31;
    const uint32_t sb = smem_u32(sm);
    int*   rtok  = (int*)(sm + 4 * G2_STAGE);
    float* rcoef = (float*)(sm + 4 * G2_STAGE + 512);
    if (tid < 128) { rtok[tid] = g_tok[r0 + tid]; rcoef[tid] = g_coef[r0 + tid]; }
    __syncthreads();

    const int lr = tid >> 3, lc = tid & 7;
    const uint32_t as0 = swz(lr * 128 + lc * 16);
    const float* ah[4];
    #pragma unroll
    for (int j = 0; j < 4; j++) ah[j] = g_h + (size_t)(r0 + lr + 32 * j) * INTER + lc * 4;
    const float* bg = w2 + ((size_t)e * HIDDEN + n0 + lr) * INTER + lc * 4;

    auto issueStage = [&](int st, int kc) {
        uint32_t base = sb + st * G2_STAGE;
        int k0 = kc * KC;
        #pragma unroll
        for (int j = 0; j < 4; j++) CP_ASYNC16(base + as0 + 4096 * j, ah[j] + k0);
        #pragma unroll
        for (int j = 0; j < 8; j++) CP_ASYNC16(base + 16384 + as0 + 4096 * j, bg + (size_t)(32 * j) * INTER + k0);
    };

    const int mw = wid & 1, nw = wid >> 1;       // warp = 64M x 64N
    const int r = lane >> 2, q = lane & 3;
    const uint32_t r16 = (uint32_t)r << 4;
    float acc[4][8][4] = {};

    issueStage(0, 0); CP_COMMIT();
    issueStage(1, 1); CP_COMMIT();
    issueStage(2, 2); CP_COMMIT();

    const int NCk = INTER / KC;   // 128
    for (int kc = 0; kc < NCk; kc++) {
        const int st = kc & 3;
        CP_WAIT2();
        __syncthreads();
        const bool pf = (kc + 3 < NCk);
        const uint32_t pbase = sb + ((kc + 3) & 3) * G2_STAGE;
        const int pk0 = (kc + 3) * KC;
        const char* Ab = sm + st * G2_STAGE + mw * 8192 + r * 128;
        const char* Bb = sm + st * G2_STAGE + 16384 + nw * 8192 + r * 128;
        #pragma unroll
        for (int k8 = 0; k8 < 4; k8++) {
            const uint32_t c0 = (uint32_t)((k8 * 8 + q) * 4) ^ r16;
            const uint32_t c1 = c0 ^ 16u;
            uint32_t a[4][4];
            #pragma unroll
            for (int i = 0; i < 4; i++) {
                a[i][0] = *(const uint32_t*)(Ab + i * 2048 + c0);
                a[i][1] = *(const uint32_t*)(Ab + i * 2048 + 1024 + c0);
                a[i][2] = *(const uint32_t*)(Ab + i * 2048 + c1);
                a[i][3] = *(const uint32_t*)(Ab + i * 2048 + 1024 + c1);
            }
            uint32_t br[16];
            #pragma unroll
            for (int j = 0; j < 8; j++) {
                br[2 * j]     = *(const uint32_t*)(Bb + j * 1024 + c0);
                br[2 * j + 1] = *(const uint32_t*)(Bb + j * 1024 + c1);
            }
            // spread prefetch: 3 cp.asyncs of stage kc+3 per k8 (A slice k8, B slices 2k8, 2k8+1)
            if (pf) {
                CP_ASYNC16(pbase + as0 + 4096 * k8, ah[k8] + pk0);
                CP_ASYNC16(pbase + 16384 + as0 + 4096 * (2 * k8),     bg + (size_t)(32 * (2 * k8)) * INTER + pk0);
                CP_ASYNC16(pbase + 16384 + as0 + 4096 * (2 * k8 + 1), bg + (size_t)(32 * (2 * k8 + 1)) * INTER + pk0);
            }
            #pragma unroll
            for (int j = 0; j < 8; j++) {
                uint32_t b0 = cvt_frag(br[2 * j]);
                uint32_t b1 = cvt_frag(br[2 * j + 1]);
                #pragma unroll
                for (int i = 0; i < 4; i++) mma8(acc[i][j], a[i], b0, b1);
            }
        }
        CP_COMMIT();
    }

    // epilogue: atomic scatter with routing coefficient
    #pragma unroll
    for (int i = 0; i < 4; i++) {
        int rl = mw * 64 + i * 16 + r;
        float cf0 = rcoef[rl], cf1 = rcoef[rl + 8];
        int   tk0 = rtok[rl],  tk1 = rtok[rl + 8];
        #pragma unroll
        for (int j = 0; j < 8; j++) {
            int cg = n0 + nw * 64 + j * 8 + q * 2;
            if (cf0 != 0.f) {
                float* p = out + (size_t)tk0 * HIDDEN + cg;
                atomicAdd(p,     cf0 * acc[i][j][0]);
                atomicAdd(p + 1, cf0 * acc[i][j][1]);
            }
            if (cf1 != 0.f) {
                float* p = out + (size_t)tk1 * HIDDEN + cg;
                atomicAdd(p,     cf1 * acc[i][j][2]);
                atomicAdd(p + 1, cf1 * acc[i][j][3]);
            }
        }
    }
}

// ---------------- launch ----------------
extern "C" void kernel_launch(void* const* d_in, const int* in_sizes, int n_in,
                              void* d_out, int out_size) {
    const float* x  = (const float*)d_in[0];
    const float* gw = (const float*)d_in[1];
    const float* w1 = (const float*)d_in[2];
    const float* w2 = (const float*)d_in[3];
    const float* w3 = (const float*)d_in[4];
    float* out = (float*)d_out;

    cudaFuncSetAttribute(gemm1_kernel, cudaFuncAttributeMaxDynamicSharedMemorySize, G1_SMEMSZ);
    cudaFuncSetAttribute(gemm2_kernel, cudaFuncAttributeMaxDynamicSharedMemorySize, G2_SMEMSZ);

    // launch order keeps gemm1 at ncu's capture slot (5th launch)
    cudaMemsetAsync(d_out, 0, (size_t)TOKENS * HIDDEN * sizeof(float), 0);   // 1
    cvt_x_kernel<<<(unsigned)(XELEMS / 4 / 256), 256>>>((const float4*)x);   // 2 (zeroes g_counts too)
    router_kernel<<<TOKENS, 256>>>(x, gw);                                   // 3
    build_lists_kernel<<<NE, 256>>>();                                       // 4
    gemm1_kernel<<<dim3(INTER / 128, MT), 256, G1_SMEMSZ>>>(w1, w3);         // 5 <- profiled
    gemm2_kernel<<<dim3(HIDDEN / 256, MT), 256, G2_SMEMSZ>>>(w2, out);       // 6
}

// round 17
// speedup vs baseline: 1.7008x; 1.0654x over previous
#include <cuda_runtime.h>
#include <cstdint>
#include <math.h>

#define NE      8
#define HIDDEN  2048
#define INTER   4096
#define TOKENS  8192
#define SLOTS   (TOKENS * 2)
#define PADM    128
#define SLOTS_PAD (SLOTS + NE * PADM)   // 17408
#define MT      (SLOTS_PAD / PADM)      // 136
#define KC      32                      // K elems per pipeline chunk
#define XELEMS  ((size_t)TOKENS * HIDDEN)

// ---------------- scratch (device globals: allocation-free, ~352 MB total) ----------------
__device__ int   g_topk_idx[SLOTS];
__device__ float g_topk_w[SLOTS];
__device__ int   g_counts[NE];
__device__ int   g_off[NE + 1];
__device__ int   g_tok[SLOTS_PAD];
__device__ float g_coef[SLOTS_PAD];
__device__ float g_h[(size_t)SLOTS_PAD * INTER];   // ~285 MB
__device__ float g_xt[XELEMS];                     // tf32-rounded x (~67 MB)

// ---------------- helpers ----------------
__device__ __forceinline__ uint32_t smem_u32(const void* p) {
    uint32_t a;
    asm("{ .reg .u64 t; cvta.to.shared.u64 t, %1; cvt.u32.u64 %0, t; }" : "=r"(a) : "l"(p));
    return a;
}
__device__ __forceinline__ uint32_t swz(uint32_t off) { return off ^ ((off >> 3) & 0x70); }

__device__ __forceinline__ float rna_tf32(float f) {
    uint32_t r;
    asm("cvt.rna.tf32.f32 %0, %1;" : "=r"(r) : "f"(f));
    return __uint_as_float(r);
}
__device__ __forceinline__ uint32_t cvt_frag(uint32_t raw) {
    uint32_t r;
    asm("cvt.rna.tf32.f32 %0, %1;" : "=r"(r) : "f"(__uint_as_float(raw)));
    return r;
}
__device__ __forceinline__ uint4 tf32x4(float4 v) {
    uint4 r;
    asm("cvt.rna.tf32.f32 %0, %1;" : "=r"(r.x) : "f"(v.x));
    asm("cvt.rna.tf32.f32 %0, %1;" : "=r"(r.y) : "f"(v.y));
    asm("cvt.rna.tf32.f32 %0, %1;" : "=r"(r.z) : "f"(v.z));
    asm("cvt.rna.tf32.f32 %0, %1;" : "=r"(r.w) : "f"(v.w));
    return r;
}

#define CP_ASYNC16(s, g) asm volatile("cp.async.cg.shared.global [%0], [%1], 16;" :: "r"(s), "l"(g))
#define CP_COMMIT()      asm volatile("cp.async.commit_group;" ::: "memory")
#define CP_WAIT1()       asm volatile("cp.async.wait_group 1;" ::: "memory")

// m16n8k8 tf32 mma: D/C fp32, A row-major, B col-major
__device__ __forceinline__ void mma8(float* c, const uint32_t* a, uint32_t b0, uint32_t b1) {
    asm volatile(
        "mma.sync.aligned.m16n8k8.row.col.f32.tf32.tf32.f32 "
        "{%0,%1,%2,%3},{%4,%5,%6,%7},{%8,%9},{%0,%1,%2,%3};"
        : "+f"(c[0]), "+f"(c[1]), "+f"(c[2]), "+f"(c[3])
        : "r"(a[0]), "r"(a[1]), "r"(a[2]), "r"(a[3]), "r"(b0), "r"(b1));
}

// ---------------- zero counts (tiny; keeps gemm1 at ncu capture slot 5) ----------------
__global__ void zero_counts_kernel() { if (threadIdx.x < NE) g_counts[threadIdx.x] = 0; }

// ---------------- router: logits/top2 + fused x->tf32 conversion + counting ----------------
__global__ __launch_bounds__(256) void router_kernel(const float* __restrict__ x,
                                                     const float* __restrict__ gw) {
    __shared__ float xs[HIDDEN];
    __shared__ float logits[NE];
    int t = blockIdx.x, tid = threadIdx.x;
    const float* xr = x + (size_t)t * HIDDEN;
    for (int i = tid; i < HIDDEN; i += 256) xs[i] = xr[i];
    __syncthreads();
    // fused: write tf32-rounded x row (cvt_x pass eliminated)
    {
        float* xtr = g_xt + (size_t)t * HIDDEN;
        #pragma unroll
        for (int v = 0; v < 2; v++) {
            int i = (tid + v * 256) * 4;
            float4 f = *(const float4*)(xs + i);
            uint4 o = tf32x4(f);
            *(float4*)(xtr + i) = *(float4*)&o;
        }
    }
    int w = tid >> 5, lane = tid & 31;
    const float* gr = gw + (size_t)w * HIDDEN;
    float s = 0.f;
    for (int i = lane; i < HIDDEN; i += 32) s += xs[i] * gr[i];
    #pragma unroll
    for (int o = 16; o; o >>= 1) s += __shfl_xor_sync(0xffffffffu, s, o);
    if (lane == 0) logits[w] = s;
    __syncthreads();
    if (tid == 0) {
        float m = logits[0];
        #pragma unroll
        for (int e = 1; e < NE; e++) m = fmaxf(m, logits[e]);
        float p[NE]; float sum = 0.f;
        #pragma unroll
        for (int e = 0; e < NE; e++) { p[e] = __expf(logits[e] - m); sum += p[e]; }
        float inv = 1.f / sum;
        #pragma unroll
        for (int e = 0; e < NE; e++) p[e] *= inv;
        int i1 = 0;
        #pragma unroll
        for (int e = 1; e < NE; e++) if (p[e] > p[i1]) i1 = e;
        int i2 = (i1 == 0) ? 1 : 0;
        #pragma unroll
        for (int e = 0; e < NE; e++) if (e != i1 && e != i2 && p[e] > p[i2]) i2 = e;
        g_topk_idx[2 * t] = i1;     g_topk_w[2 * t] = p[i1];
        g_topk_idx[2 * t + 1] = i2; g_topk_w[2 * t + 1] = p[i2];
        atomicAdd(&g_counts[i1], 1);
        atomicAdd(&g_counts[i2], 1);
    }
}

// build lists; each block also derives the expert offsets locally
__global__ __launch_bounds__(256) void build_lists_kernel() {
    int e = blockIdx.x, tid = threadIdx.x, lane = tid & 31, wid = tid >> 5;
    __shared__ int wsum[8]; __shared__ int sbase; __shared__ int seg_end;
    if (tid == 0) {
        int o = 0, my = 0, tot = 0;
        #pragma unroll
        for (int i = 0; i < NE; i++) {
            int pad = ((g_counts[i] + PADM - 1) / PADM) * PADM;
            if (i == e) my = o;
            o += pad;
            if (i == e) tot = o;
        }
        sbase = my;
        seg_end = tot;
        g_off[e] = my;
        if (e == NE - 1) g_off[NE] = o;
    }
    __syncthreads();
    int seg0 = sbase, segend = seg_end;
    for (int base = 0; base < TOKENS; base += 256) {
        int t = base + tid; int match = 0; float c = 0.f;
        int i0 = g_topk_idx[2 * t], i1 = g_topk_idx[2 * t + 1];
        if (i0 == e) { match = 1; c = g_topk_w[2 * t]; }
        else if (i1 == e) { match = 1; c = g_topk_w[2 * t + 1]; }
        unsigned m = __ballot_sync(0xffffffffu, match);
        if (lane == 0) wsum[wid] = __popc(m);
        __syncthreads();
        int woff = 0, tot = 0;
        #pragma unroll
        for (int i = 0; i < 8; i++) { int v = wsum[i]; if (i < wid) woff += v; tot += v; }
        if (match) { int p = sbase + woff + __popc(m & ((1u << lane) - 1)); g_tok[p] = t; g_coef[p] = c; }
        __syncthreads();
        if (tid == 0) sbase += tot;
        __syncthreads();
    }
    for (int p = seg0 + g_counts[e] + tid; p < segend; p += 256) { g_tok[p] = 0; g_coef[p] = 0.f; }
}

// ---------------- GEMM1: g_h = silu(x@w1^T) * (x@w3^T) ----------------
// CTA tile: M=128, N=128 (each of w1,w3). 4-stage cp.async + spread prefetch (R16)
// + double-banked fragment registers pipelined across k8 (load k8+1 during mma of k8;
// at k8=3 load next chunk's first fragments — wait_group 1 guarantees stage kc+1 resident).
#define G1_STAGE  49152
#define G1_SMEMSZ (4 * G1_STAGE + 512)

__global__ __launch_bounds__(256, 1) void gemm1_kernel(const float* __restrict__ w1,
                                                       const float* __restrict__ w3) {
    extern __shared__ char sm[];
    const int r0 = blockIdx.y * PADM;
    if (r0 >= g_off[NE]) return;
    int e = 0;
    #pragma unroll
    for (int i = 1; i < NE; i++) if (r0 >= g_off[i]) e = i;
    const int n0 = blockIdx.x * 128;
    const int tid = threadIdx.x, wid = tid >> 5, lane = tid & 31;
    const uint32_t sb = smem_u32(sm);
    int* rtok = (int*)(sm + 4 * G1_STAGE);
    if (tid < 128) rtok[tid] = g_tok[r0 + tid];
    __syncthreads();

    const int lr = tid >> 3, lc = tid & 7;
    const uint32_t as0 = swz(lr * 128 + lc * 16);
    const float* agx[4];
    #pragma unroll
    for (int j = 0; j < 4; j++) agx[j] = g_xt + (size_t)rtok[lr + 32 * j] * HIDDEN + lc * 4;
    const float* b1g = w1 + ((size_t)e * INTER + n0 + lr) * HIDDEN + lc * 4;
    const float* b3g = w3 + ((size_t)e * INTER + n0 + lr) * HIDDEN + lc * 4;

    auto issueStage = [&](int st, int kc) {
        uint32_t base = sb + st * G1_STAGE;
        int k0 = kc * KC;
        #pragma unroll
        for (int j = 0; j < 4; j++) CP_ASYNC16(base + as0 + 4096 * j, agx[j] + k0);
        #pragma unroll
        for (int j = 0; j < 4; j++) CP_ASYNC16(base + 16384 + as0 + 4096 * j, b1g + (size_t)(32 * j) * HIDDEN + k0);
        #pragma unroll
        for (int j = 0; j < 4; j++) CP_ASYNC16(base + 32768 + as0 + 4096 * j, b3g + (size_t)(32 * j) * HIDDEN + k0);
    };

    const int mw = wid & 1, nw = wid >> 1;       // warp = 64M x 32N (per matrix)
    const int r = lane >> 2, q = lane & 3;
    const uint32_t r16 = (uint32_t)r << 4;
    float accg[4][4][4] = {}, accu[4][4][4] = {};

    uint32_t afr[2][16], bfr[2][16];             // double-banked fragments (raw)
    auto loadFrag = [&](int buf, const char* stg, int k8) {
        const char* Ab  = stg + mw * 8192 + r * 128;
        const char* B1b = stg + 16384 + nw * 4096 + r * 128;
        const char* B3b = B1b + 16384;
        const uint32_t c0 = (uint32_t)((k8 * 8 + q) * 4) ^ r16;
        const uint32_t c1 = c0 ^ 16u;
        #pragma unroll
        for (int i = 0; i < 4; i++) {
            afr[buf][4*i+0] = *(const uint32_t*)(Ab + i * 2048 + c0);
            afr[buf][4*i+1] = *(const uint32_t*)(Ab + i * 2048 + 1024 + c0);
            afr[buf][4*i+2] = *(const uint32_t*)(Ab + i * 2048 + c1);
            afr[buf][4*i+3] = *(const uint32_t*)(Ab + i * 2048 + 1024 + c1);
        }
        #pragma unroll
        for (int j = 0; j < 4; j++) {
            bfr[buf][2*j]     = *(const uint32_t*)(B1b + j * 1024 + c0);
            bfr[buf][2*j+1]   = *(const uint32_t*)(B1b + j * 1024 + c1);
            bfr[buf][8+2*j]   = *(const uint32_t*)(B3b + j * 1024 + c0);
            bfr[buf][8+2*j+1] = *(const uint32_t*)(B3b + j * 1024 + c1);
        }
    };
    auto compute = [&](int buf) {
        #pragma unroll
        for (int j = 0; j < 4; j++) {
            uint32_t b1a = cvt_frag(bfr[buf][2*j]);
            uint32_t b1c = cvt_frag(bfr[buf][2*j+1]);
            uint32_t b3a = cvt_frag(bfr[buf][8+2*j]);
            uint32_t b3c = cvt_frag(bfr[buf][8+2*j+1]);
            #pragma unroll
            for (int i = 0; i < 4; i++) {
                mma8(accg[i][j], &afr[buf][4*i], b1a, b1c);
                mma8(accu[i][j], &afr[buf][4*i], b3a, b3c);
            }
        }
    };

    issueStage(0, 0); CP_COMMIT();
    issueStage(1, 1); CP_COMMIT();
    issueStage(2, 2); CP_COMMIT();
    CP_WAIT1();                      // stages 0,1 resident
    __syncthreads();
    loadFrag(0, sm, 0);              // chunk 0, k8=0

    const int NCk = HIDDEN / KC;     // 64
    for (int kc = 0; kc < NCk; kc++) {
        if (kc) { CP_WAIT1(); __syncthreads(); }   // stages <= kc+1 resident
        const char* curS = sm + (kc & 3) * G1_STAGE;
        const char* nxtS = sm + ((kc + 1) & 3) * G1_STAGE;
        const bool pf = (kc + 3 < NCk);
        const uint32_t pbase = sb + ((kc + 3) & 3) * G1_STAGE;
        const int pk0 = (kc + 3) * KC;
        #pragma unroll
        for (int k8 = 0; k8 < 4; k8++) {
            if (k8 < 3) loadFrag((k8 + 1) & 1, curS, k8 + 1);
            else        loadFrag(0, nxtS, 0);       // next chunk's first fragments
            if (pf) {                               // spread prefetch (3 cp.async / k8)
                CP_ASYNC16(pbase + as0 + 4096 * k8, agx[k8] + pk0);
                CP_ASYNC16(pbase + 16384 + as0 + 4096 * k8, b1g + (size_t)(32 * k8) * HIDDEN + pk0);
                CP_ASYNC16(pbase + 32768 + as0 + 4096 * k8, b3g + (size_t)(32 * k8) * HIDDEN + pk0);
            }
            compute(k8 & 1);
        }
        CP_COMMIT();                 // one group per chunk (empty at tail)
    }

    // epilogue: h = rna(silu(g) * u), stored tf32-rounded for gemm2
    #pragma unroll
    for (int i = 0; i < 4; i++) {
        int row0 = r0 + mw * 64 + i * 16 + r;
        #pragma unroll
        for (int j = 0; j < 4; j++) {
            int cg = n0 + nw * 32 + j * 8 + q * 2;
            float g0 = accg[i][j][0], g1 = accg[i][j][1], g2 = accg[i][j][2], g3 = accg[i][j][3];
            float u0 = accu[i][j][0], u1 = accu[i][j][1], u2 = accu[i][j][2], u3 = accu[i][j][3];
            float h0 = rna_tf32((g0 / (1.f + __expf(-g0))) * u0);
            float h1 = rna_tf32((g1 / (1.f + __expf(-g1))) * u1);
            float h2 = rna_tf32((g2 / (1.f + __expf(-g2))) * u2);
            float h3 = rna_tf32((g3 / (1.f + __expf(-g3))) * u3);
            *(float2*)(g_h + (size_t)row0 * INTER + cg)       = make_float2(h0, h1);
            *(float2*)(g_h + (size_t)(row0 + 8) * INTER + cg) = make_float2(h2, h3);
        }
    }
}

// ---------------- GEMM2: out[tok] += coef * (h @ w2^T) ----------------
// CTA tile: M=128, N=256. Same: 4-stage, spread prefetch, double-banked fragments.
#define G2_STAGE  49152
#define G2_SMEMSZ (4 * G2_STAGE + 1024)

__global__ __launch_bounds__(256, 1) void gemm2_kernel(const float* __restrict__ w2,
                                                       float* __restrict__ out) {
    extern __shared__ char sm[];
    const int r0 = blockIdx.y * PADM;
    if (r0 >= g_off[NE]) return;
    int e = 0;
    #pragma unroll
    for (int i = 1; i < NE; i++) if (r0 >= g_off[i]) e = i;
    const int n0 = blockIdx.x * 256;
    const int tid = threadIdx.x, wid = tid >> 5, lane = tid & 31;
    const uint32_t sb = smem_u32(sm);
    int*   rtok  = (int*)(sm + 4 * G2_STAGE);
    float* rcoef = (float*)(sm + 4 * G2_STAGE + 512);
    if (tid < 128) { rtok[tid] = g_tok[r0 + tid]; rcoef[tid] = g_coef[r0 + tid]; }
    __syncthreads();

    const int lr = tid >> 3, lc = tid & 7;
    const uint32_t as0 = swz(lr * 128 + lc * 16);
    const float* ah[4];
    #pragma unroll
    for (int j = 0; j < 4; j++) ah[j] = g_h + (size_t)(r0 + lr + 32 * j) * INTER + lc * 4;
    const float* bg = w2 + ((size_t)e * HIDDEN + n0 + lr) * INTER + lc * 4;

    auto issueStage = [&](int st, int kc) {
        uint32_t base = sb + st * G2_STAGE;
        int k0 = kc * KC;
        #pragma unroll
        for (int j = 0; j < 4; j++) CP_ASYNC16(base + as0 + 4096 * j, ah[j] + k0);
        #pragma unroll
        for (int j = 0; j < 8; j++) CP_ASYNC16(base + 16384 + as0 + 4096 * j, bg + (size_t)(32 * j) * INTER + k0);
    };

    const int mw = wid & 1, nw = wid >> 1;       // warp = 64M x 64N
    const int r = lane >> 2, q = lane & 3;
    const uint32_t r16 = (uint32_t)r << 4;
    float acc[4][8][4] = {};

    uint32_t afr[2][16], bfr[2][16];
    auto loadFrag = [&](int buf, const char* stg, int k8) {
        const char* Ab = stg + mw * 8192 + r * 128;
        const char* Bb = stg + 16384 + nw * 8192 + r * 128;
        const uint32_t c0 = (uint32_t)((k8 * 8 + q) * 4) ^ r16;
        const uint32_t c1 = c0 ^ 16u;
        #pragma unroll
        for (int i = 0; i < 4; i++) {
            afr[buf][4*i+0] = *(const uint32_t*)(Ab + i * 2048 + c0);
            afr[buf][4*i+1] = *(const uint32_t*)(Ab + i * 2048 + 1024 + c0);
            afr[buf][4*i+2] = *(const uint32_t*)(Ab + i * 2048 + c1);
            afr[buf][4*i+3] = *(const uint32_t*)(Ab + i * 2048 + 1024 + c1);
        }
        #pragma unroll
        for (int j = 0; j < 8; j++) {
            bfr[buf][2*j]   = *(const uint32_t*)(Bb + j * 1024 + c0);
            bfr[buf][2*j+1] = *(const uint32_t*)(Bb + j * 1024 + c1);
        }
    };
    auto compute = [&](int buf) {
        #pragma unroll
        for (int j = 0; j < 8; j++) {
            uint32_t b0 = cvt_frag(bfr[buf][2*j]);
            uint32_t b1 = cvt_frag(bfr[buf][2*j+1]);
            #pragma unroll
            for (int i = 0; i < 4; i++) mma8(acc[i][j], &afr[buf][4*i], b0, b1);
        }
    };

    issueStage(0, 0); CP_COMMIT();
    issueStage(1, 1); CP_COMMIT();
    issueStage(2, 2); CP_COMMIT();
    CP_WAIT1();
    __syncthreads();
    loadFrag(0, sm, 0);

    const int NCk = INTER / KC;   // 128
    for (int kc = 0; kc < NCk; kc++) {
        if (kc) { CP_WAIT1(); __syncthreads(); }
        const char* curS = sm + (kc & 3) * G2_STAGE;
        const char* nxtS = sm + ((kc + 1) & 3) * G2_STAGE;
        const bool pf = (kc + 3 < NCk);
        const uint32_t pbase = sb + ((kc + 3) & 3) * G2_STAGE;
        const int pk0 = (kc + 3) * KC;
        #pragma unroll
        for (int k8 = 0; k8 < 4; k8++) {
            if (k8 < 3) loadFrag((k8 + 1) & 1, curS, k8 + 1);
            else        loadFrag(0, nxtS, 0);
            if (pf) {
                CP_ASYNC16(pbase + as0 + 4096 * k8, ah[k8] + pk0);
                CP_ASYNC16(pbase + 16384 + as0 + 4096 * (2 * k8),     bg + (size_t)(32 * (2 * k8)) * INTER + pk0);
                CP_ASYNC16(pbase + 16384 + as0 + 4096 * (2 * k8 + 1), bg + (size_t)(32 * (2 * k8 + 1)) * INTER + pk0);
            }
            compute(k8 & 1);
        }
        CP_COMMIT();
    }

    // epilogue: atomic scatter with routing coefficient
    #pragma unroll
    for (int i = 0; i < 4; i++) {
        int rl = mw * 64 + i * 16 + r;
        float cf0 = rcoef[rl], cf1 = rcoef[rl + 8];
        int   tk0 = rtok[rl],  tk1 = rtok[rl + 8];
        #pragma unroll
        for (int j = 0; j < 8; j++) {
            int cg = n0 + nw * 64 + j * 8 + q * 2;
            if (cf0 != 0.f) {
                float* p = out + (size_t)tk0 * HIDDEN + cg;
                atomicAdd(p,     cf0 * acc[i][j][0]);
                atomicAdd(p + 1, cf0 * acc[i][j][1]);
            }
            if (cf1 != 0.f) {
                float* p = out + (size_t)tk1 * HIDDEN + cg;
                atomicAdd(p,     cf1 * acc[i][j][2]);
                atomicAdd(p + 1, cf1 * acc[i][j][3]);
            }
        }
    }
}

// ---------------- launch ----------------
extern "C" void kernel_launch(void* const* d_in, const int* in_sizes, int n_in,
                              void* d_out, int out_size) {
    const float* x  = (const float*)d_in[0];
    const float* gw = (const float*)d_in[1];
    const float* w1 = (const float*)d_in[2];
    const float* w2 = (const float*)d_in[3];
    const float* w3 = (const float*)d_in[4];
    float* out = (float*)d_out;

    cudaFuncSetAttribute(gemm1_kernel, cudaFuncAttributeMaxDynamicSharedMemorySize, G1_SMEMSZ);
    cudaFuncSetAttribute(gemm2_kernel, cudaFuncAttributeMaxDynamicSharedMemorySize, G2_SMEMSZ);

    // launch order keeps gemm1 at ncu's capture slot (5th launch)
    cudaMemsetAsync(d_out, 0, (size_t)TOKENS * HIDDEN * sizeof(float), 0);   // 1
    zero_counts_kernel<<<1, 32>>>();                                         // 2
    router_kernel<<<TOKENS, 256>>>(x, gw);                                   // 3 (also writes g_xt)
    build_lists_kernel<<<NE, 256>>>();                                       // 4
    gemm1_kernel<<<dim3(INTER / 128, MT), 256, G1_SMEMSZ>>>(w1, w3);         // 5 <- profiled
    gemm2_kernel<<<dim3(HIDDEN / 256, MT), 256, G2_SMEMSZ>>>(w2, out);       // 6
}